// round 1
// baseline (speedup 1.0000x reference)
#include <cuda_runtime.h>
#include <math.h>

#define BATCH 128
#define WDIM  512
#define HDIM  512
#define NOUT  1536            // [f(512) | o(512) | a(512)]
#define K2_SPLITS 8

// ---------------- scratch (device globals: allocation-free rule) -------------
__device__ __align__(16) float g_havg[BATCH * HDIM];
__device__ __align__(16) float g_f[BATCH * HDIM];
__device__ __align__(16) float g_o[BATCH * HDIM];
__device__ __align__(16) float g_a[BATCH * HDIM];
__device__ __align__(16) float g_part[K2_SPLITS * BATCH * NOUT];

// ---------------- K1: h_avg[b,j] = mean_w h[b,w,j] ---------------------------
__global__ void k_havg(const float* __restrict__ h)
{
    int idx = blockIdx.x * blockDim.x + threadIdx.x;   // 0..65535
    int b = idx >> 9;
    int j = idx & 511;
    const float* p = h + b * (WDIM * HDIM) + j;
    float s = 0.f;
#pragma unroll 8
    for (int w = 0; w < WDIM; ++w) s += p[w * HDIM];
    g_havg[idx] = s * (1.0f / WDIM);
}

// ---------------- K2: split-K GEMM for [fo | a] -------------------------------
// C[b, j] over j in [0,1536), K = 1024 effective:
//   A[b,k] = k<512 ? g[b,k] : h_avg[b,k-512]
//   B[j,k] : j<1024 -> (k<512 ? W_w[j,k] : U_w[j,k-512])
//            j>=1024 -> (k<512 ? w_w[j-1024,k] : 0)
__global__ void __launch_bounds__(256)
k_fo(const float* __restrict__ g, const float* __restrict__ W_w,
     const float* __restrict__ U_w, const float* __restrict__ w_w)
{
    __shared__ __align__(16) float As[16 * 132];
    __shared__ __align__(16) float Bs[16 * 132];

    int nt  = blockIdx.x;   // 0..11 : 128-wide j tile
    int ks  = blockIdx.y;   // 0..7  : K split
    int tid = threadIdx.x;
    int tx  = tid & 15;     // col group: jj = tx*8 + s
    int ty  = tid >> 4;     // row group: bb = ty*8 + r

    float acc[8][8];
#pragma unroll
    for (int r = 0; r < 8; ++r)
#pragma unroll
        for (int s = 0; s < 8; ++s) acc[r][s] = 0.f;

    const int kbase = ks * 128;
    const int q  = tid & 3;
    const int lr = tid >> 2;   // 0..63

    for (int kk = 0; kk < 128; kk += 16) {
        // ---- load A tile (128 b x 16 k), stored As[kc][b] ----
#pragma unroll
        for (int p = 0; p < 2; ++p) {
            int b  = p * 64 + lr;
            int kg = kbase + kk + q * 4;
            float4 v;
            if (kg < 512) v = *(const float4*)(g + b * 512 + kg);
            else          v = *(const float4*)(&g_havg[b * 512 + (kg - 512)]);
            float* dst = &As[(q * 4) * 132 + b];
            dst[0]       = v.x;
            dst[132]     = v.y;
            dst[2 * 132] = v.z;
            dst[3 * 132] = v.w;
        }
        // ---- load B tile (128 j x 16 k), stored Bs[kc][jj] ----
#pragma unroll
        for (int p = 0; p < 2; ++p) {
            int jj = p * 64 + lr;
            int j  = nt * 128 + jj;
            int kg = kbase + kk + q * 4;
            float4 v;
            if (j < 1024) {
                if (kg < 512) v = *(const float4*)(W_w + j * 512 + kg);
                else          v = *(const float4*)(U_w + j * 512 + (kg - 512));
            } else {
                if (kg < 512) v = *(const float4*)(w_w + (j - 1024) * 512 + kg);
                else          v = make_float4(0.f, 0.f, 0.f, 0.f);
            }
            float* dst = &Bs[(q * 4) * 132 + jj];
            dst[0]       = v.x;
            dst[132]     = v.y;
            dst[2 * 132] = v.z;
            dst[3 * 132] = v.w;
        }
        __syncthreads();

#pragma unroll
        for (int kc = 0; kc < 16; ++kc) {
            float4 a0 = *(const float4*)&As[kc * 132 + ty * 8];
            float4 a1 = *(const float4*)&As[kc * 132 + ty * 8 + 4];
            float4 b0 = *(const float4*)&Bs[kc * 132 + tx * 8];
            float4 b1 = *(const float4*)&Bs[kc * 132 + tx * 8 + 4];
            float av[8] = {a0.x, a0.y, a0.z, a0.w, a1.x, a1.y, a1.z, a1.w};
            float bv[8] = {b0.x, b0.y, b0.z, b0.w, b1.x, b1.y, b1.z, b1.w};
#pragma unroll
            for (int r = 0; r < 8; ++r)
#pragma unroll
                for (int s = 0; s < 8; ++s) acc[r][s] += av[r] * bv[s];
        }
        __syncthreads();
    }

    // ---- store partials ----
#pragma unroll
    for (int r = 0; r < 8; ++r) {
        int bb = ty * 8 + r;
        float* dst = &g_part[(ks * 128 + bb) * NOUT + nt * 128 + tx * 8];
        *(float4*)dst       = make_float4(acc[r][0], acc[r][1], acc[r][2], acc[r][3]);
        *(float4*)(dst + 4) = make_float4(acc[r][4], acc[r][5], acc[r][6], acc[r][7]);
    }
}

// ---------------- K2b: reduce splits + bias + activation ---------------------
__global__ void k_fo_fin(const float* __restrict__ U_b)
{
    int idx = blockIdx.x * blockDim.x + threadIdx.x;   // 0..196607
    int b = idx / NOUT;
    int j = idx - b * NOUT;
    float s = 0.f;
#pragma unroll
    for (int ks = 0; ks < K2_SPLITS; ++ks)
        s += g_part[(ks * 128 + b) * NOUT + j];
    if (j < 1024) {
        s += U_b[j];
        s = 1.f / (1.f + __expf(-s));
        if (j < 512) g_f[b * 512 + j] = s;
        else         g_o[b * 512 + (j - 512)] = s;
    } else {
        g_a[b * 512 + (j - 1024)] = s;
    }
}

// ---------------- K3: fused GEMM + sigmoid + softmax(W) + weighted c sum -----
// Per CTA: batch b, 32-wide H tile. S[w][t] kept entirely in SMEM.
#define K3_S_STRIDE 33
#define K3_A_STRIDE 17
#define K3_SMEM_FLOATS (512*33 + 512*17 + 32*17 + 8*32 + 32 + 32)
#define K3_SMEM_BYTES  (K3_SMEM_FLOATS * 4)

__global__ void __launch_bounds__(256, 2)
k_main(const float* __restrict__ h, const float* __restrict__ c,
       const float* __restrict__ u_w, const float* __restrict__ u_b,
       const float* __restrict__ c_g, float* __restrict__ out)
{
    extern __shared__ float sm[];
    float* S      = sm;                          // [512][33]
    float* At     = S + 512 * K3_S_STRIDE;       // [512][17]
    float* Bt     = At + 512 * K3_A_STRIDE;      // [32][17]
    float* red    = Bt + 32 * K3_A_STRIDE;       // [8][32]
    float* colmax = red + 8 * 32;                // [32]
    float* colinv = colmax + 32;                 // [32]

    const int b   = blockIdx.y;
    const int ht0 = blockIdx.x * 32;
    const int tid = threadIdx.x;
    const int tt  = tid & 3;     // col group: t = tt*8 + j
    const int tw  = tid >> 2;    // row group: w = tw + 64*i

    const float* hb = h + b * (WDIM * HDIM);

    float acc[8][8];
#pragma unroll
    for (int i = 0; i < 8; ++i)
#pragma unroll
        for (int j = 0; j < 8; ++j) acc[i][j] = 0.f;

    const int q  = tid & 3;
    const int wr = tid >> 2;

    for (int k0 = 0; k0 < 512; k0 += 16) {
        // load A tile: h[b, 0..511, k0..k0+16)
#pragma unroll
        for (int p = 0; p < 8; ++p) {
            int w = p * 64 + wr;
            float4 v = *(const float4*)(hb + w * 512 + k0 + q * 4);
            float* dst = &At[w * K3_A_STRIDE + q * 4];
            dst[0] = v.x; dst[1] = v.y; dst[2] = v.z; dst[3] = v.w;
        }
        // load B tile: u_w[ht0..ht0+32, k0..k0+16)
        if (tid < 128) {
            int t = tid >> 2;
            float4 v = *(const float4*)(u_w + (ht0 + t) * 512 + k0 + q * 4);
            float* dst = &Bt[t * K3_A_STRIDE + q * 4];
            dst[0] = v.x; dst[1] = v.y; dst[2] = v.z; dst[3] = v.w;
        }
        __syncthreads();

#pragma unroll
        for (int kc = 0; kc < 16; ++kc) {
            float av[8], bv[8];
#pragma unroll
            for (int i = 0; i < 8; ++i)
                av[i] = At[(tw + (i << 6)) * K3_A_STRIDE + kc];
#pragma unroll
            for (int j = 0; j < 8; ++j)
                bv[j] = Bt[(tt * 8 + j) * K3_A_STRIDE + kc];
#pragma unroll
            for (int i = 0; i < 8; ++i)
#pragma unroll
                for (int j = 0; j < 8; ++j) acc[i][j] += av[i] * bv[j];
        }
        __syncthreads();
    }

    // epilogue: add a + u_b, sigmoid, write S
    float addv[8];
#pragma unroll
    for (int j = 0; j < 8; ++j) {
        int t = tt * 8 + j;
        addv[j] = g_a[b * 512 + ht0 + t] + u_b[ht0 + t];
    }
#pragma unroll
    for (int i = 0; i < 8; ++i) {
        int w = tw + (i << 6);
#pragma unroll
        for (int j = 0; j < 8; ++j) {
            float x = acc[i][j] + addv[j];
            S[w * K3_S_STRIDE + tt * 8 + j] = 1.f / (1.f + __expf(-x));
        }
    }
    __syncthreads();

    // softmax over w (per column) + weighted sum with c
    const int col = tid & 31;
    const int seg = tid >> 5;   // 8 segments x 64 w each

    float m = -1e30f;
#pragma unroll 8
    for (int ww = 0; ww < 64; ++ww)
        m = fmaxf(m, S[(seg * 64 + ww) * K3_S_STRIDE + col]);
    red[seg * 32 + col] = m;
    __syncthreads();
    if (seg == 0) {
        float mm = red[col];
#pragma unroll
        for (int s2 = 1; s2 < 8; ++s2) mm = fmaxf(mm, red[s2 * 32 + col]);
        colmax[col] = mm;
    }
    __syncthreads();

    const float mm = colmax[col];
    float ds = 0.f;
#pragma unroll 8
    for (int ww = 0; ww < 64; ++ww) {
        int w = seg * 64 + ww;
        float e = __expf(S[w * K3_S_STRIDE + col] - mm);
        S[w * K3_S_STRIDE + col] = e;   // reuse S to hold exp values
        ds += e;
    }
    red[seg * 32 + col] = ds;
    __syncthreads();
    if (seg == 0) {
        float t = 0.f;
#pragma unroll
        for (int s2 = 0; s2 < 8; ++s2) t += red[s2 * 32 + col];
        colinv[col] = 1.0f / t;
    }
    __syncthreads();

    const float inv = colinv[col];
    const float* cb = c + b * (WDIM * HDIM) + ht0 + col;
    float ws = 0.f;
#pragma unroll 8
    for (int ww = 0; ww < 64; ++ww) {
        int w = seg * 64 + ww;
        ws += S[w * K3_S_STRIDE + col] * cb[w * 512];
    }
    __syncthreads();           // all reads of red done before rewrite
    red[seg * 32 + col] = ws;
    __syncthreads();
    if (seg == 0) {
        float tot = 0.f;
#pragma unroll
        for (int s2 = 0; s2 < 8; ++s2) tot += red[s2 * 32 + col];
        tot *= inv;
        int gi = b * 512 + ht0 + col;
        float newc = g_f[gi] * c_g[gi] + tot;
        out[65536 + gi] = newc;              // new_c (second output)
        out[gi] = g_o[gi] * tanhf(newc);     // new_g (first output)
    }
}

// ---------------- launch ------------------------------------------------------
extern "C" void kernel_launch(void* const* d_in, const int* in_sizes, int n_in,
                              void* d_out, int out_size)
{
    const float* g   = (const float*)d_in[0];
    const float* c_g = (const float*)d_in[1];
    const float* h   = (const float*)d_in[2];
    const float* c   = (const float*)d_in[3];
    const float* W_w = (const float*)d_in[4];
    const float* w_w = (const float*)d_in[5];
    const float* U_w = (const float*)d_in[6];
    const float* U_b = (const float*)d_in[7];
    const float* u_w = (const float*)d_in[8];
    const float* u_b = (const float*)d_in[9];
    float* out = (float*)d_out;

    (void)in_sizes; (void)n_in; (void)out_size;

    k_havg<<<256, 256>>>(h);
    k_fo<<<dim3(12, 8), 256>>>(g, W_w, U_w, w_w);
    k_fo_fin<<<768, 256>>>(U_b);

    cudaFuncSetAttribute(k_main, cudaFuncAttributeMaxDynamicSharedMemorySize,
                         K3_SMEM_BYTES);
    k_main<<<dim3(16, 128), 256, K3_SMEM_BYTES>>>(h, c, u_w, u_b, c_g, out);
}

// round 2
// speedup vs baseline: 2.2465x; 2.2465x over previous
#include <cuda_runtime.h>
#include <math.h>
#include <stdint.h>

#define BATCH 128
#define WDIM  512
#define HDIM  512
#define WH    (WDIM * HDIM)
#define NOUT  1536            // [f(512) | o(512) | a(512)]
#define K2_SPLITS 8

// ---------------- scratch (device globals: allocation-free rule) -------------
__device__ __align__(16) float g_havg[BATCH * HDIM];
__device__ __align__(16) float g_f[BATCH * HDIM];
__device__ __align__(16) float g_o[BATCH * HDIM];
__device__ __align__(16) float g_a[BATCH * HDIM];
__device__ __align__(16) float g_part[K2_SPLITS * BATCH * NOUT];

// ---------------- FMA-only fast math (avoid MUFU pipe) -----------------------
__device__ __forceinline__ float fast_exp(float x)
{
    // exp(x) = 2^(x * log2(e)) ; FMA-only, ~1e-7 rel err
    float y = x * 1.44269504089f;
    y = fminf(fmaxf(y, -125.0f), 125.0f);
    float z = y + 12582912.0f;                       // round-to-nearest trick
    int   n = __float_as_int(z) - 0x4B400000;
    float f = y - (z - 12582912.0f);                 // f in [-0.5, 0.5]
    float t = f * 0.69314718056f;                    // |t| <= 0.3466
    float p = 0.0013888889f;
    p = fmaf(p, t, 0.0083333333f);
    p = fmaf(p, t, 0.0416666667f);
    p = fmaf(p, t, 0.1666666667f);
    p = fmaf(p, t, 0.5f);
    p = fmaf(p, t, 1.0f);
    p = fmaf(p, t, 1.0f);
    return __int_as_float(__float_as_int(p) + (n << 23));
}

__device__ __forceinline__ float fast_rcp(float d)
{
    // bit-trick seed + 3 Newton steps, FMA-only
    float r = __int_as_float(0x7EF311C3 - __float_as_int(d));
    r = r * (2.0f - d * r);
    r = r * (2.0f - d * r);
    r = r * (2.0f - d * r);
    return r;
}

__device__ __forceinline__ float exp_sigmoid(float x)
{
    // exp(sigmoid(x)); sigmoid in (0,1) so no overflow concerns downstream
    float t = fast_exp(-x);
    float s = fast_rcp(1.0f + t);
    return fast_exp(s);
}

// ---------------- tf32 mma helpers -------------------------------------------
__device__ __forceinline__ uint32_t to_tf32(float x)
{
    uint32_t u;
    asm("cvt.rna.tf32.f32 %0, %1;" : "=r"(u) : "f"(x));
    return u;
}

__device__ __forceinline__ void mma_tf32(float* d, const uint32_t* a, const uint32_t* b)
{
    asm volatile(
        "mma.sync.aligned.m16n8k8.row.col.f32.tf32.tf32.f32 "
        "{%0,%1,%2,%3}, {%4,%5,%6,%7}, {%8,%9}, {%0,%1,%2,%3};"
        : "+f"(d[0]), "+f"(d[1]), "+f"(d[2]), "+f"(d[3])
        : "r"(a[0]), "r"(a[1]), "r"(a[2]), "r"(a[3]),
          "r"(b[0]), "r"(b[1]));
}

// ---------------- K1: h_avg[b,j] = mean_w h[b,w,j] ---------------------------
__global__ void k_havg(const float* __restrict__ h)
{
    int idx = blockIdx.x * blockDim.x + threadIdx.x;   // 0..65535
    int b = idx >> 9;
    int j = idx & 511;
    const float* p = h + (size_t)b * WH + j;
    float s = 0.f;
#pragma unroll 8
    for (int w = 0; w < WDIM; ++w) s += p[(size_t)w * HDIM];
    g_havg[idx] = s * (1.0f / WDIM);
}

// ---------------- K2: split-K fp32 GEMM for [fo | a] --------------------------
__global__ void __launch_bounds__(256)
k_fo(const float* __restrict__ g, const float* __restrict__ W_w,
     const float* __restrict__ U_w, const float* __restrict__ w_w)
{
    __shared__ __align__(16) float As[16 * 132];
    __shared__ __align__(16) float Bs[16 * 132];

    int nt  = blockIdx.x;   // 0..11
    int ks  = blockIdx.y;   // 0..7
    int tid = threadIdx.x;
    int tx  = tid & 15;
    int ty  = tid >> 4;

    float acc[8][8];
#pragma unroll
    for (int r = 0; r < 8; ++r)
#pragma unroll
        for (int s = 0; s < 8; ++s) acc[r][s] = 0.f;

    const int kbase = ks * 128;
    const int q  = tid & 3;
    const int lr = tid >> 2;

    for (int kk = 0; kk < 128; kk += 16) {
#pragma unroll
        for (int p = 0; p < 2; ++p) {
            int b  = p * 64 + lr;
            int kg = kbase + kk + q * 4;
            float4 v;
            if (kg < 512) v = *(const float4*)(g + b * 512 + kg);
            else          v = *(const float4*)(&g_havg[b * 512 + (kg - 512)]);
            float* dst = &As[(q * 4) * 132 + b];
            dst[0] = v.x; dst[132] = v.y; dst[2*132] = v.z; dst[3*132] = v.w;
        }
#pragma unroll
        for (int p = 0; p < 2; ++p) {
            int jj = p * 64 + lr;
            int j  = nt * 128 + jj;
            int kg = kbase + kk + q * 4;
            float4 v;
            if (j < 1024) {
                if (kg < 512) v = *(const float4*)(W_w + j * 512 + kg);
                else          v = *(const float4*)(U_w + j * 512 + (kg - 512));
            } else {
                if (kg < 512) v = *(const float4*)(w_w + (j - 1024) * 512 + kg);
                else          v = make_float4(0.f, 0.f, 0.f, 0.f);
            }
            float* dst = &Bs[(q * 4) * 132 + jj];
            dst[0] = v.x; dst[132] = v.y; dst[2*132] = v.z; dst[3*132] = v.w;
        }
        __syncthreads();

#pragma unroll
        for (int kc = 0; kc < 16; ++kc) {
            float4 a0 = *(const float4*)&As[kc * 132 + ty * 8];
            float4 a1 = *(const float4*)&As[kc * 132 + ty * 8 + 4];
            float4 b0 = *(const float4*)&Bs[kc * 132 + tx * 8];
            float4 b1 = *(const float4*)&Bs[kc * 132 + tx * 8 + 4];
            float av[8] = {a0.x, a0.y, a0.z, a0.w, a1.x, a1.y, a1.z, a1.w};
            float bv[8] = {b0.x, b0.y, b0.z, b0.w, b1.x, b1.y, b1.z, b1.w};
#pragma unroll
            for (int r = 0; r < 8; ++r)
#pragma unroll
                for (int s = 0; s < 8; ++s) acc[r][s] += av[r] * bv[s];
        }
        __syncthreads();
    }

#pragma unroll
    for (int r = 0; r < 8; ++r) {
        int bb = ty * 8 + r;
        float* dst = &g_part[(ks * 128 + bb) * NOUT + nt * 128 + tx * 8];
        *(float4*)dst       = make_float4(acc[r][0], acc[r][1], acc[r][2], acc[r][3]);
        *(float4*)(dst + 4) = make_float4(acc[r][4], acc[r][5], acc[r][6], acc[r][7]);
    }
}

// ---------------- K2b: reduce splits + bias + activation ---------------------
__global__ void k_fo_fin(const float* __restrict__ U_b)
{
    int idx = blockIdx.x * blockDim.x + threadIdx.x;   // 0..196607
    int b = idx / NOUT;
    int j = idx - b * NOUT;
    float s = 0.f;
#pragma unroll
    for (int ks = 0; ks < K2_SPLITS; ++ks)
        s += g_part[(ks * 128 + b) * NOUT + j];
    if (j < 1024) {
        s += U_b[j];
        s = fast_rcp(1.f + fast_exp(-s));
        if (j < 512) g_f[b * 512 + j] = s;
        else         g_o[b * 512 + (j - 512)] = s;
    } else {
        g_a[b * 512 + (j - 1024)] = s;
    }
}

// ---------------- K3: tf32 tensor-core GEMM + fused softmax ------------------
// Per CTA: batch b, 64-wide H tile. M=512(W) x N=64 x K=512, tf32 mma.sync.
// S (512x64) lives in SMEM (aliasing GEMM staging buffers), softmax over W and
// the weighted-c reduction fused into one pass.
#define SB_STRIDE 20              // conflict-free for frag LDS pattern
#define S_STRIDE  65
#define OFF_AS0   0
#define OFF_AS1   (512 * SB_STRIDE)            // 10240
#define OFF_BS0   (2 * 512 * SB_STRIDE)        // 20480
#define OFF_BS1   (OFF_BS0 + 64 * SB_STRIDE)   // 21760
#define OFF_S     0                            // aliases AS/BS (disjoint lifetimes)
#define OFF_ADD   (512 * S_STRIDE)             // 33280
#define OFF_R1    (OFF_ADD + 64)
#define OFF_R2    (OFF_R1 + 512)
#define K3_SMEM_FLOATS (OFF_R2 + 512)          // 34368
#define K3_SMEM_BYTES  (K3_SMEM_FLOATS * 4)    // 137472

__device__ __forceinline__ void ldg_chunk(const float* __restrict__ hb,
                                          const float* __restrict__ u_w,
                                          int ht0, int tid, int k0,
                                          float4 av[4], float4& bv)
{
    const int arow = tid >> 2;
    const int aq   = tid & 3;
#pragma unroll
    for (int p = 0; p < 4; ++p)
        av[p] = *(const float4*)(hb + (size_t)(arow + 128 * p) * HDIM + k0 + aq * 4);
    if (tid < 256)
        bv = *(const float4*)(u_w + (size_t)(ht0 + arow) * HDIM + k0 + aq * 4);
}

__device__ __forceinline__ void sts_chunk(float* sm, int basA, int basB,
                                          int tid, const float4 av[4], const float4& bv)
{
    const int arow = tid >> 2;
    const int aq   = tid & 3;
#pragma unroll
    for (int p = 0; p < 4; ++p) {
        float* d = &sm[basA + (arow + 128 * p) * SB_STRIDE + aq * 4];
        d[0] = __uint_as_float(to_tf32(av[p].x));
        d[1] = __uint_as_float(to_tf32(av[p].y));
        d[2] = __uint_as_float(to_tf32(av[p].z));
        d[3] = __uint_as_float(to_tf32(av[p].w));
    }
    if (tid < 256) {
        float* d = &sm[basB + arow * SB_STRIDE + aq * 4];
        d[0] = __uint_as_float(to_tf32(bv.x));
        d[1] = __uint_as_float(to_tf32(bv.y));
        d[2] = __uint_as_float(to_tf32(bv.z));
        d[3] = __uint_as_float(to_tf32(bv.w));
    }
}

__global__ void __launch_bounds__(512, 1)
k_main(const float* __restrict__ h, const float* __restrict__ c,
       const float* __restrict__ u_w, const float* __restrict__ u_b,
       const float* __restrict__ c_g, float* __restrict__ out)
{
    extern __shared__ float sm[];
    const int b    = blockIdx.y;
    const int ht0  = blockIdx.x * 64;
    const int tid  = threadIdx.x;
    const int wid  = tid >> 5;
    const int lane = tid & 31;
    const int wm   = wid >> 1;        // 0..7 : 64-row M block
    const int wn   = wid & 1;         // 0..1 : 32-col N block
    const int g4   = lane >> 2;       // groupID
    const int t4   = lane & 3;        // thread-in-group

    const float* hb = h + (size_t)b * WH;

    if (tid < 64)
        sm[OFF_ADD + tid] = g_a[b * HDIM + ht0 + tid] + u_b[ht0 + tid];

    float acc[4][4][4];
#pragma unroll
    for (int i = 0; i < 4; ++i)
#pragma unroll
        for (int j = 0; j < 4; ++j)
#pragma unroll
            for (int r = 0; r < 4; ++r) acc[i][j][r] = 0.f;

    float4 av[4];
    float4 bv = make_float4(0.f, 0.f, 0.f, 0.f);

    // prologue: chunk 0
    ldg_chunk(hb, u_w, ht0, tid, 0, av, bv);
    sts_chunk(sm, OFF_AS0, OFF_BS0, tid, av, bv);
    __syncthreads();

    for (int ch = 0; ch < 32; ++ch) {
        const int cur = ch & 1;
        if (ch < 31) ldg_chunk(hb, u_w, ht0, tid, (ch + 1) * 16, av, bv);

        const int asb = cur ? OFF_AS1 : OFF_AS0;
        const int bsb = cur ? OFF_BS1 : OFF_BS0;

#pragma unroll
        for (int s = 0; s < 2; ++s) {
            const int kk0 = s * 8;
            uint32_t af[4][4];
#pragma unroll
            for (int tm = 0; tm < 4; ++tm) {
                int r0 = wm * 64 + tm * 16 + g4;
                const float* p0 = &sm[asb + r0 * SB_STRIDE + kk0 + t4];
                af[tm][0] = __float_as_uint(p0[0]);
                af[tm][1] = __float_as_uint(p0[8 * SB_STRIDE]);
                af[tm][2] = __float_as_uint(p0[4]);
                af[tm][3] = __float_as_uint(p0[8 * SB_STRIDE + 4]);
            }
            uint32_t bf[4][2];
#pragma unroll
            for (int tn = 0; tn < 4; ++tn) {
                int t0 = wn * 32 + tn * 8 + g4;
                const float* p0 = &sm[bsb + t0 * SB_STRIDE + kk0 + t4];
                bf[tn][0] = __float_as_uint(p0[0]);
                bf[tn][1] = __float_as_uint(p0[4]);
            }
#pragma unroll
            for (int tm = 0; tm < 4; ++tm)
#pragma unroll
                for (int tn = 0; tn < 4; ++tn)
                    mma_tf32(acc[tm][tn], af[tm], bf[tn]);
        }

        if (ch < 31) sts_chunk(sm, cur ? OFF_AS0 : OFF_AS1, cur ? OFF_BS0 : OFF_BS1,
                               tid, av, bv);
        __syncthreads();
    }

    // epilogue: x -> exp(sigmoid(x)) -> S   (S region aliases AS/BS, GEMM done)
#pragma unroll
    for (int tm = 0; tm < 4; ++tm) {
#pragma unroll
        for (int tn = 0; tn < 4; ++tn) {
            int colb = wn * 32 + tn * 8 + t4 * 2;
            float add0 = sm[OFF_ADD + colb];
            float add1 = sm[OFF_ADD + colb + 1];
#pragma unroll
            for (int r = 0; r < 2; ++r) {
                int w = wm * 64 + tm * 16 + g4 + r * 8;
                float x0 = acc[tm][tn][r * 2 + 0] + add0;
                float x1 = acc[tm][tn][r * 2 + 1] + add1;
                sm[OFF_S + w * S_STRIDE + colb]     = exp_sigmoid(x0);
                sm[OFF_S + w * S_STRIDE + colb + 1] = exp_sigmoid(x1);
            }
        }
    }
    __syncthreads();

    // fused: softmax denominator + weighted-c numerator in one pass
    const int col = tid & 63;
    const int seg = tid >> 6;     // 8 segments x 64 w
    const float* cb = c + (size_t)b * WH + ht0 + col;
    float ds = 0.f, ws = 0.f;
#pragma unroll 8
    for (int ww = 0; ww < 64; ++ww) {
        int w = seg * 64 + ww;
        float e  = sm[OFF_S + w * S_STRIDE + col];
        float cv = cb[(size_t)w * HDIM];
        ds += e;
        ws += e * cv;
    }
    sm[OFF_R1 + seg * 64 + col] = ds;
    sm[OFF_R2 + seg * 64 + col] = ws;
    __syncthreads();

    if (tid < 64) {
        float dt = 0.f, wt = 0.f;
#pragma unroll
        for (int s2 = 0; s2 < 8; ++s2) {
            dt += sm[OFF_R1 + s2 * 64 + tid];
            wt += sm[OFF_R2 + s2 * 64 + tid];
        }
        int gi = b * HDIM + ht0 + tid;
        float newc = g_f[gi] * c_g[gi] + wt / dt;
        out[BATCH * HDIM + gi] = newc;            // new_c
        out[gi] = g_o[gi] * tanhf(newc);          // new_g
    }
}

// ---------------- launch ------------------------------------------------------
extern "C" void kernel_launch(void* const* d_in, const int* in_sizes, int n_in,
                              void* d_out, int out_size)
{
    const float* g   = (const float*)d_in[0];
    const float* c_g = (const float*)d_in[1];
    const float* h   = (const float*)d_in[2];
    const float* c   = (const float*)d_in[3];
    const float* W_w = (const float*)d_in[4];
    const float* w_w = (const float*)d_in[5];
    const float* U_w = (const float*)d_in[6];
    const float* U_b = (const float*)d_in[7];
    const float* u_w = (const float*)d_in[8];
    const float* u_b = (const float*)d_in[9];
    float* out = (float*)d_out;

    (void)in_sizes; (void)n_in; (void)out_size;

    k_havg<<<256, 256>>>(h);
    k_fo<<<dim3(12, 8), 256>>>(g, W_w, U_w, w_w);
    k_fo_fin<<<768, 256>>>(U_b);

    static int smem_set = 0;
    if (!smem_set) {
        cudaFuncSetAttribute(k_main, cudaFuncAttributeMaxDynamicSharedMemorySize,
                             K3_SMEM_BYTES);
        smem_set = 1;
    }
    k_main<<<dim3(8, 128), 512, K3_SMEM_BYTES>>>(h, c, u_w, u_b, c_g, out);
}

// round 3
// speedup vs baseline: 3.4850x; 1.5513x over previous
#include <cuda_runtime.h>
#include <math.h>
#include <stdint.h>

#define BATCH 128
#define WDIM  512
#define HDIM  512
#define WH    (WDIM * HDIM)
#define NOUT  1536            // [f(512) | o(512) | a(512)]
#define K2_SPLITS 8

// ---------------- scratch (device globals: allocation-free rule) -------------
__device__ __align__(16) float g_havg[BATCH * HDIM];
__device__ __align__(16) float g_f[BATCH * HDIM];
__device__ __align__(16) float g_o[BATCH * HDIM];
__device__ __align__(16) float g_a[BATCH * HDIM];
__device__ __align__(16) float g_part[K2_SPLITS * BATCH * NOUT];

// ---------------- FMA-only fast math (avoid MUFU pipe) -----------------------
__device__ __forceinline__ float fast_exp(float x)
{
    float y = x * 1.44269504089f;
    y = fminf(fmaxf(y, -125.0f), 125.0f);
    float z = y + 12582912.0f;                       // round-to-nearest trick
    int   n = __float_as_int(z) - 0x4B400000;
    float f = y - (z - 12582912.0f);                 // f in [-0.5, 0.5]
    float t = f * 0.69314718056f;
    float p = 0.0013888889f;
    p = fmaf(p, t, 0.0083333333f);
    p = fmaf(p, t, 0.0416666667f);
    p = fmaf(p, t, 0.1666666667f);
    p = fmaf(p, t, 0.5f);
    p = fmaf(p, t, 1.0f);
    p = fmaf(p, t, 1.0f);
    return __int_as_float(__float_as_int(p) + (n << 23));
}

__device__ __forceinline__ float fast_rcp(float d)
{
    float r = __int_as_float(0x7EF311C3 - __float_as_int(d));
    r = r * (2.0f - d * r);
    r = r * (2.0f - d * r);
    r = r * (2.0f - d * r);
    return r;
}

__device__ __forceinline__ float exp_sigmoid(float x)
{
    float t = fast_exp(-x);
    float s = fast_rcp(1.0f + t);
    return fast_exp(s);
}

// ---------------- mma / ldmatrix / cp.async helpers ---------------------------
__device__ __forceinline__ void mma_tf32(float* d, const uint32_t* a, const uint32_t* b)
{
    asm volatile(
        "mma.sync.aligned.m16n8k8.row.col.f32.tf32.tf32.f32 "
        "{%0,%1,%2,%3}, {%4,%5,%6,%7}, {%8,%9}, {%0,%1,%2,%3};"
        : "+f"(d[0]), "+f"(d[1]), "+f"(d[2]), "+f"(d[3])
        : "r"(a[0]), "r"(a[1]), "r"(a[2]), "r"(a[3]),
          "r"(b[0]), "r"(b[1]));
}

__device__ __forceinline__ void ldsm_x4(uint32_t* r, uint32_t addr)
{
    asm volatile("ldmatrix.sync.aligned.m8n8.x4.shared.b16 {%0,%1,%2,%3}, [%4];"
                 : "=r"(r[0]), "=r"(r[1]), "=r"(r[2]), "=r"(r[3]) : "r"(addr));
}

__device__ __forceinline__ void ldsm_x2(uint32_t* r, uint32_t addr)
{
    asm volatile("ldmatrix.sync.aligned.m8n8.x2.shared.b16 {%0,%1}, [%2];"
                 : "=r"(r[0]), "=r"(r[1]) : "r"(addr));
}

__device__ __forceinline__ void cp16(uint32_t saddr, const float* g)
{
    asm volatile("cp.async.cg.shared.global [%0], [%1], 16;" :: "r"(saddr), "l"(g));
}
__device__ __forceinline__ void cp_commit()
{
    asm volatile("cp.async.commit_group;" ::: "memory");
}
template<int N> __device__ __forceinline__ void cp_wait()
{
    asm volatile("cp.async.wait_group %0;" :: "n"(N) : "memory");
}

// ---------------- K1: h_avg[b,j] = mean_w h[b,w,j] ---------------------------
__global__ void k_havg(const float* __restrict__ h)
{
    int idx = blockIdx.x * blockDim.x + threadIdx.x;   // 0..65535
    int b = idx >> 9;
    int j = idx & 511;
    const float* p = h + (size_t)b * WH + j;
    float s = 0.f;
#pragma unroll 8
    for (int w = 0; w < WDIM; ++w) s += p[(size_t)w * HDIM];
    g_havg[idx] = s * (1.0f / WDIM);
}

// ---------------- K2: split-K fp32 GEMM for [fo | a] --------------------------
__global__ void __launch_bounds__(256)
k_fo(const float* __restrict__ g, const float* __restrict__ W_w,
     const float* __restrict__ U_w, const float* __restrict__ w_w)
{
    __shared__ __align__(16) float As[16 * 132];
    __shared__ __align__(16) float Bs[16 * 132];

    int nt  = blockIdx.x;
    int ks  = blockIdx.y;
    int tid = threadIdx.x;
    int tx  = tid & 15;
    int ty  = tid >> 4;

    float acc[8][8];
#pragma unroll
    for (int r = 0; r < 8; ++r)
#pragma unroll
        for (int s = 0; s < 8; ++s) acc[r][s] = 0.f;

    const int kbase = ks * 128;
    const int q  = tid & 3;
    const int lr = tid >> 2;

    for (int kk = 0; kk < 128; kk += 16) {
#pragma unroll
        for (int p = 0; p < 2; ++p) {
            int b  = p * 64 + lr;
            int kg = kbase + kk + q * 4;
            float4 v;
            if (kg < 512) v = *(const float4*)(g + b * 512 + kg);
            else          v = *(const float4*)(&g_havg[b * 512 + (kg - 512)]);
            float* dst = &As[(q * 4) * 132 + b];
            dst[0] = v.x; dst[132] = v.y; dst[2*132] = v.z; dst[3*132] = v.w;
        }
#pragma unroll
        for (int p = 0; p < 2; ++p) {
            int jj = p * 64 + lr;
            int j  = nt * 128 + jj;
            int kg = kbase + kk + q * 4;
            float4 v;
            if (j < 1024) {
                if (kg < 512) v = *(const float4*)(W_w + j * 512 + kg);
                else          v = *(const float4*)(U_w + j * 512 + (kg - 512));
            } else {
                if (kg < 512) v = *(const float4*)(w_w + (j - 1024) * 512 + kg);
                else          v = make_float4(0.f, 0.f, 0.f, 0.f);
            }
            float* dst = &Bs[(q * 4) * 132 + jj];
            dst[0] = v.x; dst[132] = v.y; dst[2*132] = v.z; dst[3*132] = v.w;
        }
        __syncthreads();

#pragma unroll
        for (int kc = 0; kc < 16; ++kc) {
            float4 a0 = *(const float4*)&As[kc * 132 + ty * 8];
            float4 a1 = *(const float4*)&As[kc * 132 + ty * 8 + 4];
            float4 b0 = *(const float4*)&Bs[kc * 132 + tx * 8];
            float4 b1 = *(const float4*)&Bs[kc * 132 + tx * 8 + 4];
            float av[8] = {a0.x, a0.y, a0.z, a0.w, a1.x, a1.y, a1.z, a1.w};
            float bv[8] = {b0.x, b0.y, b0.z, b0.w, b1.x, b1.y, b1.z, b1.w};
#pragma unroll
            for (int r = 0; r < 8; ++r)
#pragma unroll
                for (int s = 0; s < 8; ++s) acc[r][s] += av[r] * bv[s];
        }
        __syncthreads();
    }

#pragma unroll
    for (int r = 0; r < 8; ++r) {
        int bb = ty * 8 + r;
        float* dst = &g_part[(ks * 128 + bb) * NOUT + nt * 128 + tx * 8];
        *(float4*)dst       = make_float4(acc[r][0], acc[r][1], acc[r][2], acc[r][3]);
        *(float4*)(dst + 4) = make_float4(acc[r][4], acc[r][5], acc[r][6], acc[r][7]);
    }
}

// ---------------- K2b: reduce splits + bias + activation ---------------------
__global__ void k_fo_fin(const float* __restrict__ U_b)
{
    int idx = blockIdx.x * blockDim.x + threadIdx.x;
    int b = idx / NOUT;
    int j = idx - b * NOUT;
    float s = 0.f;
#pragma unroll
    for (int ks = 0; ks < K2_SPLITS; ++ks)
        s += g_part[(ks * 128 + b) * NOUT + j];
    if (j < 1024) {
        s += U_b[j];
        s = fast_rcp(1.f + fast_exp(-s));
        if (j < 512) g_f[b * 512 + j] = s;
        else         g_o[b * 512 + (j - 512)] = s;
    } else {
        g_a[b * 512 + (j - 1024)] = s;
    }
}

// ---------------- K3: tf32 mma + ldmatrix + cp.async + fused softmax ---------
// Per CTA: (b, 64-wide H tile). M=512(W) x N=64 x K=512.
// K chunks of 32 (128B rows), XOR-swizzled, 2-stage cp.async pipeline.
#define KCH     32
#define NCHUNK  16
#define OFF_A   0            // A stage: 512 rows x 32 floats; x2 stages
#define A_STG   16384
#define OFF_B   32768        // B stage: 64 rows x 32 floats; x2 stages
#define B_STG   2048
#define OFF_ADD 36864
#define OFF_R1  36928
#define OFF_R2  37440
#define K3_SMEM_FLOATS 37952
#define K3_SMEM_BYTES  (K3_SMEM_FLOATS * 4)   // 151808
#define S_STRIDE 65          // S[512][65] aliases stage buffers (disjoint lifetime)

__global__ void __launch_bounds__(512, 1)
k_main(const float* __restrict__ h, const float* __restrict__ c,
       const float* __restrict__ u_w, const float* __restrict__ u_b,
       const float* __restrict__ c_g, float* __restrict__ out)
{
    extern __shared__ float sm[];
    const uint32_t smb = (uint32_t)__cvta_generic_to_shared(sm);

    const int b    = blockIdx.y;
    const int ht0  = blockIdx.x * 64;
    const int tid  = threadIdx.x;
    const int wid  = tid >> 5;
    const int lane = tid & 31;
    const int wm   = wid >> 1;        // 0..7 : 64-row M block
    const int wn   = wid & 1;         // 0..1 : 32-col N block
    const int g4   = lane >> 2;
    const int t4   = lane & 3;

    const float* hb = h + (size_t)b * WH;

    if (tid < 64)
        sm[OFF_ADD + tid] = g_a[b * HDIM + ht0 + tid] + u_b[ht0 + tid];

    // ---- cp.async staging (row = 32 floats = 128B, swizzle quad^(row&7)) ----
    const int crow = tid >> 3;        // 0..63
    const int cq   = tid & 7;

    auto load_chunk = [&](int ch, int st) {
        const float* gA = hb + ch * KCH + cq * 4;
        const uint32_t sA = smb + (OFF_A + st * A_STG) * 4;
#pragma unroll
        for (int p = 0; p < 8; ++p) {
            int row = crow + p * 64;
            cp16(sA + (uint32_t)(row * 32 + ((cq ^ (row & 7)) * 4)) * 4,
                 gA + (size_t)row * HDIM);
        }
        const float* gB = u_w + (size_t)(ht0 + crow) * HDIM + ch * KCH + cq * 4;
        cp16(smb + (uint32_t)(OFF_B + st * B_STG + crow * 32 +
                              ((cq ^ (crow & 7)) * 4)) * 4, gB);
    };

    // ---- ldmatrix per-lane base addresses ----
    const int lane15 = lane & 15;
    const int laneQA = lane >> 4;          // 0/1 -> k-quad +0/+1 (A, x4)
    const int laneB7 = lane & 7;
    const int laneQB = (lane >> 3) & 1;    // 0/1 -> k-quad +0/+1 (B, x2)

    uint32_t aBase[4]; uint32_t aRL[4];
#pragma unroll
    for (int tm = 0; tm < 4; ++tm) {
        int row = wm * 64 + tm * 16 + lane15;
        aRL[tm]   = row & 7;
        aBase[tm] = smb + (uint32_t)(OFF_A + row * 32) * 4;
    }
    uint32_t bBase[4]; uint32_t bRL[4];
#pragma unroll
    for (int tn = 0; tn < 4; ++tn) {
        int row = wn * 32 + tn * 8 + laneB7;
        bRL[tn]   = row & 7;
        bBase[tn] = smb + (uint32_t)(OFF_B + row * 32) * 4;
    }

    float acc[4][4][4];
#pragma unroll
    for (int i = 0; i < 4; ++i)
#pragma unroll
        for (int j = 0; j < 4; ++j)
#pragma unroll
            for (int r = 0; r < 4; ++r) acc[i][j][r] = 0.f;

    // ---- 2-stage pipeline ----
    load_chunk(0, 0); cp_commit();
    load_chunk(1, 1); cp_commit();

    for (int ch = 0; ch < NCHUNK; ++ch) {
        const int st = ch & 1;
        if (ch == NCHUNK - 1) cp_wait<0>(); else cp_wait<1>();
        __syncthreads();

        const uint32_t offA = (uint32_t)st * (A_STG * 4);
        const uint32_t offB = (uint32_t)st * (B_STG * 4);

#pragma unroll
        for (int kk = 0; kk < 4; ++kk) {
            const uint32_t qb = (uint32_t)(kk * 2);
            uint32_t af[4][4], bf[4][2];
#pragma unroll
            for (int tm = 0; tm < 4; ++tm)
                ldsm_x4(af[tm], aBase[tm] + offA + (((qb + laneQA) ^ aRL[tm]) << 4));
#pragma unroll
            for (int tn = 0; tn < 4; ++tn)
                ldsm_x2(bf[tn], bBase[tn] + offB + (((qb + laneQB) ^ bRL[tn]) << 4));
#pragma unroll
            for (int tm = 0; tm < 4; ++tm)
#pragma unroll
                for (int tn = 0; tn < 4; ++tn)
                    mma_tf32(acc[tm][tn], af[tm], bf[tn]);
        }
        __syncthreads();
        if (ch + 2 < NCHUNK) { load_chunk(ch + 2, st); cp_commit(); }
    }

    // ---- epilogue: x -> exp(sigmoid(x)) -> S (aliases dead stage buffers) ----
#pragma unroll
    for (int tm = 0; tm < 4; ++tm) {
#pragma unroll
        for (int tn = 0; tn < 4; ++tn) {
            int colb = wn * 32 + tn * 8 + t4 * 2;
            float add0 = sm[OFF_ADD + colb];
            float add1 = sm[OFF_ADD + colb + 1];
#pragma unroll
            for (int r = 0; r < 2; ++r) {
                int w = wm * 64 + tm * 16 + g4 + r * 8;
                float x0 = acc[tm][tn][r * 2 + 0] + add0;
                float x1 = acc[tm][tn][r * 2 + 1] + add1;
                sm[w * S_STRIDE + colb]     = exp_sigmoid(x0);
                sm[w * S_STRIDE + colb + 1] = exp_sigmoid(x1);
            }
        }
    }
    __syncthreads();

    // ---- fused: softmax denominator + weighted-c numerator ----
    const int col = tid & 63;
    const int seg = tid >> 6;     // 8 segments x 64 w
    const float* cb = c + (size_t)b * WH + ht0 + col;
    float ds = 0.f, ws = 0.f;
#pragma unroll 8
    for (int ww = 0; ww < 64; ++ww) {
        int w = seg * 64 + ww;
        float e  = sm[w * S_STRIDE + col];
        float cv = cb[(size_t)w * HDIM];
        ds += e;
        ws += e * cv;
    }
    sm[OFF_R1 + seg * 64 + col] = ds;
    sm[OFF_R2 + seg * 64 + col] = ws;
    __syncthreads();

    if (tid < 64) {
        float dt = 0.f, wt = 0.f;
#pragma unroll
        for (int s2 = 0; s2 < 8; ++s2) {
            dt += sm[OFF_R1 + s2 * 64 + tid];
            wt += sm[OFF_R2 + s2 * 64 + tid];
        }
        int gi = b * HDIM + ht0 + tid;
        float newc = g_f[gi] * c_g[gi] + wt / dt;
        out[BATCH * HDIM + gi] = newc;            // new_c
        out[gi] = g_o[gi] * tanhf(newc);          // new_g
    }
}

// ---------------- launch ------------------------------------------------------
extern "C" void kernel_launch(void* const* d_in, const int* in_sizes, int n_in,
                              void* d_out, int out_size)
{
    const float* g   = (const float*)d_in[0];
    const float* c_g = (const float*)d_in[1];
    const float* h   = (const float*)d_in[2];
    const float* c   = (const float*)d_in[3];
    const float* W_w = (const float*)d_in[4];
    const float* w_w = (const float*)d_in[5];
    const float* U_w = (const float*)d_in[6];
    const float* U_b = (const float*)d_in[7];
    const float* u_w = (const float*)d_in[8];
    const float* u_b = (const float*)d_in[9];
    float* out = (float*)d_out;

    (void)in_sizes; (void)n_in; (void)out_size;

    k_havg<<<256, 256>>>(h);
    k_fo<<<dim3(12, 8), 256>>>(g, W_w, U_w, w_w);
    k_fo_fin<<<768, 256>>>(U_b);

    static int smem_set = 0;
    if (!smem_set) {
        cudaFuncSetAttribute(k_main, cudaFuncAttributeMaxDynamicSharedMemorySize,
                             K3_SMEM_BYTES);
        smem_set = 1;
    }
    k_main<<<dim3(8, 128), 512, K3_SMEM_BYTES>>>(h, c, u_w, u_b, c_g, out);
}

// round 5
// speedup vs baseline: 3.9391x; 1.1303x over previous
#include <cuda_runtime.h>
#include <cuda_fp16.h>
#include <math.h>
#include <stdint.h>

#define BATCH 128
#define WDIM  512
#define HDIM  512
#define WH    (WDIM * HDIM)
#define NOUT  1536
#define K2_SPLITS 8

// ---------------- scratch (device globals: allocation-free rule) -------------
__device__ __align__(16) float  g_havg[BATCH * HDIM];
__device__ __align__(16) float  g_f[BATCH * HDIM];
__device__ __align__(16) float  g_o[BATCH * HDIM];
__device__ __align__(16) float  g_a[BATCH * HDIM];
__device__ __align__(16) float  g_part[K2_SPLITS * BATCH * NOUT];
__device__ __align__(16) __half g_h16[BATCH * WH];        // fp16 copy of h
__device__ __align__(16) __half g_uw16[HDIM * HDIM];      // fp16 copy of u_w

// ---------------- FMA-only fast math -------------------------------------------
__device__ __forceinline__ float fast_exp(float x)
{
    float y = x * 1.44269504089f;
    y = fminf(fmaxf(y, -125.0f), 125.0f);
    float z = y + 12582912.0f;
    int   n = __float_as_int(z) - 0x4B400000;
    float f = y - (z - 12582912.0f);
    float t = f * 0.69314718056f;
    float p = 0.0013888889f;
    p = fmaf(p, t, 0.0083333333f);
    p = fmaf(p, t, 0.0416666667f);
    p = fmaf(p, t, 0.1666666667f);
    p = fmaf(p, t, 0.5f);
    p = fmaf(p, t, 1.0f);
    p = fmaf(p, t, 1.0f);
    return __int_as_float(__float_as_int(p) + (n << 23));
}
__device__ __forceinline__ float fast_rcp(float d)
{
    float r = __int_as_float(0x7EF311C3 - __float_as_int(d));
    r = r * (2.0f - d * r);
    r = r * (2.0f - d * r);
    r = r * (2.0f - d * r);
    return r;
}
__device__ __forceinline__ float exp_sigmoid(float x)
{
    float t = fast_exp(-x);
    float s = fast_rcp(1.0f + t);
    return fast_exp(s);
}

// ---------------- mma / ldmatrix / cp.async helpers ------------------------------
__device__ __forceinline__ void mma_f16(float* d, const uint32_t* a, const uint32_t* b)
{
    asm volatile(
        "mma.sync.aligned.m16n8k16.row.col.f32.f16.f16.f32 "
        "{%0,%1,%2,%3}, {%4,%5,%6,%7}, {%8,%9}, {%0,%1,%2,%3};"
        : "+f"(d[0]), "+f"(d[1]), "+f"(d[2]), "+f"(d[3])
        : "r"(a[0]), "r"(a[1]), "r"(a[2]), "r"(a[3]),
          "r"(b[0]), "r"(b[1]));
}
__device__ __forceinline__ void ldsm_x4(uint32_t* r, uint32_t addr)
{
    asm volatile("ldmatrix.sync.aligned.m8n8.x4.shared.b16 {%0,%1,%2,%3}, [%4];"
                 : "=r"(r[0]), "=r"(r[1]), "=r"(r[2]), "=r"(r[3]) : "r"(addr));
}
__device__ __forceinline__ void ldsm_x2(uint32_t* r, uint32_t addr)
{
    asm volatile("ldmatrix.sync.aligned.m8n8.x2.shared.b16 {%0,%1}, [%2];"
                 : "=r"(r[0]), "=r"(r[1]) : "r"(addr));
}
__device__ __forceinline__ void cp16(uint32_t saddr, const void* g)
{
    asm volatile("cp.async.cg.shared.global [%0], [%1], 16;" :: "r"(saddr), "l"(g));
}
__device__ __forceinline__ void cp_commit()
{
    asm volatile("cp.async.commit_group;" ::: "memory");
}
template<int N> __device__ __forceinline__ void cp_wait()
{
    asm volatile("cp.async.wait_group %0;" :: "n"(N) : "memory");
}

// ---------------- K0: h -> fp16 + h_avg (single pass over h) ---------------------
__global__ void k_prep(const float* __restrict__ h)
{
    int idx = blockIdx.x * blockDim.x + threadIdx.x;   // 0..32767 (b, jpair)
    int b  = idx >> 8;
    int jp = idx & 255;
    const float2* p = (const float2*)(h + (size_t)b * WH) + jp;
    __half2* q = (__half2*)(g_h16 + (size_t)b * WH) + jp;
    float s0 = 0.f, s1 = 0.f;
#pragma unroll 4
    for (int w = 0; w < WDIM; ++w) {
        float2 v = p[(size_t)w * (HDIM / 2)];
        s0 += v.x; s1 += v.y;
        q[(size_t)w * (HDIM / 2)] = __floats2half2_rn(v.x, v.y);
    }
    g_havg[b * HDIM + jp * 2]     = s0 * (1.0f / WDIM);
    g_havg[b * HDIM + jp * 2 + 1] = s1 * (1.0f / WDIM);
}

// ---------------- K0b: u_w -> fp16 -----------------------------------------------
__global__ void k_convw(const float* __restrict__ u_w)
{
    int idx = blockIdx.x * blockDim.x + threadIdx.x;   // 0..131071 (pairs)
    float2 v = ((const float2*)u_w)[idx];
    ((__half2*)g_uw16)[idx] = __floats2half2_rn(v.x, v.y);
}

// ---------------- K2: split-K fp32 GEMM for [fo | a] ------------------------------
__global__ void __launch_bounds__(256)
k_fo(const float* __restrict__ g, const float* __restrict__ W_w,
     const float* __restrict__ U_w, const float* __restrict__ w_w)
{
    __shared__ __align__(16) float As[16 * 132];
    __shared__ __align__(16) float Bs[16 * 132];

    int nt  = blockIdx.x;
    int ks  = blockIdx.y;
    int tid = threadIdx.x;
    int tx  = tid & 15;
    int ty  = tid >> 4;

    float acc[8][8];
#pragma unroll
    for (int r = 0; r < 8; ++r)
#pragma unroll
        for (int s = 0; s < 8; ++s) acc[r][s] = 0.f;

    const int kbase = ks * 128;
    const int q  = tid & 3;
    const int lr = tid >> 2;

    for (int kk = 0; kk < 128; kk += 16) {
#pragma unroll
        for (int p = 0; p < 2; ++p) {
            int b  = p * 64 + lr;
            int kg = kbase + kk + q * 4;
            float4 v;
            if (kg < 512) v = *(const float4*)(g + b * 512 + kg);
            else          v = *(const float4*)(&g_havg[b * 512 + (kg - 512)]);
            float* dst = &As[(q * 4) * 132 + b];
            dst[0] = v.x; dst[132] = v.y; dst[2*132] = v.z; dst[3*132] = v.w;
        }
#pragma unroll
        for (int p = 0; p < 2; ++p) {
            int jj = p * 64 + lr;
            int j  = nt * 128 + jj;
            int kg = kbase + kk + q * 4;
            float4 v;
            if (j < 1024) {
                if (kg < 512) v = *(const float4*)(W_w + j * 512 + kg);
                else          v = *(const float4*)(U_w + j * 512 + (kg - 512));
            } else {
                if (kg < 512) v = *(const float4*)(w_w + (j - 1024) * 512 + kg);
                else          v = make_float4(0.f, 0.f, 0.f, 0.f);
            }
            float* dst = &Bs[(q * 4) * 132 + jj];
            dst[0] = v.x; dst[132] = v.y; dst[2*132] = v.z; dst[3*132] = v.w;
        }
        __syncthreads();

#pragma unroll
        for (int kc = 0; kc < 16; ++kc) {
            float4 a0 = *(const float4*)&As[kc * 132 + ty * 8];
            float4 a1 = *(const float4*)&As[kc * 132 + ty * 8 + 4];
            float4 b0 = *(const float4*)&Bs[kc * 132 + tx * 8];
            float4 b1 = *(const float4*)&Bs[kc * 132 + tx * 8 + 4];
            float av[8] = {a0.x, a0.y, a0.z, a0.w, a1.x, a1.y, a1.z, a1.w};
            float bv[8] = {b0.x, b0.y, b0.z, b0.w, b1.x, b1.y, b1.z, b1.w};
#pragma unroll
            for (int r = 0; r < 8; ++r)
#pragma unroll
                for (int s = 0; s < 8; ++s) acc[r][s] += av[r] * bv[s];
        }
        __syncthreads();
    }

#pragma unroll
    for (int r = 0; r < 8; ++r) {
        int bb = ty * 8 + r;
        float* dst = &g_part[(ks * 128 + bb) * NOUT + nt * 128 + tx * 8];
        *(float4*)dst       = make_float4(acc[r][0], acc[r][1], acc[r][2], acc[r][3]);
        *(float4*)(dst + 4) = make_float4(acc[r][4], acc[r][5], acc[r][6], acc[r][7]);
    }
}

// ---------------- K2b --------------------------------------------------------------
__global__ void k_fo_fin(const float* __restrict__ U_b)
{
    int idx = blockIdx.x * blockDim.x + threadIdx.x;
    int b = idx / NOUT;
    int j = idx - b * NOUT;
    float s = 0.f;
#pragma unroll
    for (int ks = 0; ks < K2_SPLITS; ++ks)
        s += g_part[(ks * 128 + b) * NOUT + j];
    if (j < 1024) {
        s += U_b[j];
        s = fast_rcp(1.f + fast_exp(-s));
        if (j < 512) g_f[b * 512 + j] = s;
        else         g_o[b * 512 + (j - 512)] = s;
    } else {
        g_a[b * 512 + (j - 1024)] = s;
    }
}

// ---------------- K3: fp16 mma m16n8k16 + ldmatrix + cp.async + fused softmax -----
// CTA = (b, 64-col H tile). M=512(W) x N=64 x K=512, K chunks of 64 fp16 (128B rows).
#define KCH     64
#define NCHUNK  8
// byte offsets in dynamic smem
#define OFF_ADD_F 0              // 64 floats
#define OFF_R1_F  64             // 512 floats
#define OFF_R2_F  576            // 512 floats
#define SM_STAGE_B 4608          // 128-aligned; stages: A 64KB + B 8KB, x2
#define A_BYTES    65536
#define STAGE_BYTES 73728
#define OFF_S_F   1152           // S[512][65] fp32, aliases stages (disjoint lifetime)
#define S_STRIDE  65
#define K3_SMEM_BYTES (SM_STAGE_B + 2 * STAGE_BYTES)   // 152064

__global__ void __launch_bounds__(512, 1)
k_main(const float* __restrict__ c, const float* __restrict__ u_b,
       const float* __restrict__ c_g, float* __restrict__ out)
{
    extern __shared__ __align__(128) float sm[];
    const uint32_t smb = (uint32_t)__cvta_generic_to_shared(sm);

    const int b    = blockIdx.y;
    const int ht0  = blockIdx.x * 64;
    const int tid  = threadIdx.x;
    const int wid  = tid >> 5;
    const int lane = tid & 31;
    const int wm   = wid >> 1;        // 0..7 : 64-row M block
    const int wn   = wid & 1;         // 0..1 : 32-col N block
    const int g4   = lane >> 2;
    const int t4   = lane & 3;

    const __half* hb = g_h16 + (size_t)b * WH;

    if (tid < 64)
        sm[OFF_ADD_F + tid] = g_a[b * HDIM + ht0 + tid] + u_b[ht0 + tid];

    // ---- cp.async staging: rows of 64 fp16 = 128B = 8 quads, swizzle q^(row&7) ----
    const int arow = tid >> 3;        // 0..63
    const int aq   = tid & 7;

    auto load_chunk = [&](int ch, int st) {
        const uint32_t sa = smb + SM_STAGE_B + (uint32_t)st * STAGE_BYTES;
        const __half* gA = hb + ch * KCH + aq * 8;
#pragma unroll
        for (int p = 0; p < 8; ++p) {
            int row = arow + p * 64;
            cp16(sa + (uint32_t)(row * 128 + ((aq ^ (row & 7)) << 4)),
                 gA + (size_t)row * HDIM);
        }
        // B: 64 rows x 128B
        const __half* gB = g_uw16 + (size_t)(ht0 + arow) * HDIM + ch * KCH + aq * 8;
        cp16(sa + A_BYTES + (uint32_t)(arow * 128 + ((aq ^ (arow & 7)) << 4)), gB);
        cp_commit();
    };

    // ---- ldmatrix per-lane bases ----
    const int lane15 = lane & 15;
    const int laneQA = lane >> 4;          // A x4: second 8 lanes -> next k-quad
    const int laneB7 = lane & 7;
    const int laneQB = (lane >> 3) & 1;    // B x2

    uint32_t aBase[4], aRL[4];
#pragma unroll
    for (int tm = 0; tm < 4; ++tm) {
        int row = wm * 64 + tm * 16 + lane15;
        aRL[tm]   = row & 7;
        aBase[tm] = smb + SM_STAGE_B + (uint32_t)(row * 128);
    }
    uint32_t bBase[4], bRL[4];
#pragma unroll
    for (int tn = 0; tn < 4; ++tn) {
        int row = wn * 32 + tn * 8 + laneB7;
        bRL[tn]   = row & 7;
        bBase[tn] = smb + SM_STAGE_B + A_BYTES + (uint32_t)(row * 128);
    }

    float acc[4][4][4];
#pragma unroll
    for (int i = 0; i < 4; ++i)
#pragma unroll
        for (int j = 0; j < 4; ++j)
#pragma unroll
            for (int r = 0; r < 4; ++r) acc[i][j][r] = 0.f;

    // ---- 2-stage pipeline ----
    load_chunk(0, 0);
    load_chunk(1, 1);

    for (int ch = 0; ch < NCHUNK; ++ch) {
        const int st = ch & 1;
        if (ch == NCHUNK - 1) cp_wait<0>(); else cp_wait<1>();
        __syncthreads();

        const uint32_t off = (uint32_t)st * STAGE_BYTES;
#pragma unroll
        for (int ks = 0; ks < 4; ++ks) {
            const uint32_t qb = (uint32_t)(ks * 2);
            uint32_t af[4][4], bf[4][2];
#pragma unroll
            for (int tm = 0; tm < 4; ++tm)
                ldsm_x4(af[tm], aBase[tm] + off + (((qb + laneQA) ^ aRL[tm]) << 4));
#pragma unroll
            for (int tn = 0; tn < 4; ++tn)
                ldsm_x2(bf[tn], bBase[tn] + off + (((qb + laneQB) ^ bRL[tn]) << 4));
#pragma unroll
            for (int tm = 0; tm < 4; ++tm)
#pragma unroll
                for (int tn = 0; tn < 4; ++tn)
                    mma_f16(acc[tm][tn], af[tm], bf[tn]);
        }
        __syncthreads();
        if (ch + 2 < NCHUNK) load_chunk(ch + 2, st);
    }

    // ---- epilogue: x -> exp(sigmoid(x)) -> S (aliases dead stage buffers) ----
    float* S = sm + OFF_S_F;
#pragma unroll
    for (int tm = 0; tm < 4; ++tm) {
#pragma unroll
        for (int tn = 0; tn < 4; ++tn) {
            int colb = wn * 32 + tn * 8 + t4 * 2;
            float add0 = sm[OFF_ADD_F + colb];
            float add1 = sm[OFF_ADD_F + colb + 1];
#pragma unroll
            for (int r = 0; r < 2; ++r) {
                int w = wm * 64 + tm * 16 + g4 + r * 8;
                float x0 = acc[tm][tn][r * 2 + 0] + add0;
                float x1 = acc[tm][tn][r * 2 + 1] + add1;
                S[w * S_STRIDE + colb]     = exp_sigmoid(x0);
                S[w * S_STRIDE + colb + 1] = exp_sigmoid(x1);
            }
        }
    }
    __syncthreads();

    // ---- fused: softmax denominator + weighted-c numerator ----
    const int col = tid & 63;
    const int seg = tid >> 6;     // 8 segments x 64 w
    const float* cb = c + (size_t)b * WH + ht0 + col;
    float ds = 0.f, ws = 0.f;
#pragma unroll 8
    for (int ww = 0; ww < 64; ++ww) {
        int w = seg * 64 + ww;
        float e  = S[w * S_STRIDE + col];
        float cv = cb[(size_t)w * HDIM];
        ds += e;
        ws += e * cv;
    }
    sm[OFF_R1_F + seg * 64 + col] = ds;
    sm[OFF_R2_F + seg * 64 + col] = ws;
    __syncthreads();

    if (tid < 64) {
        float dt = 0.f, wt = 0.f;
#pragma unroll
        for (int s2 = 0; s2 < 8; ++s2) {
            dt += sm[OFF_R1_F + s2 * 64 + tid];
            wt += sm[OFF_R2_F + s2 * 64 + tid];
        }
        int gi = b * HDIM + ht0 + tid;
        float newc = g_f[gi] * c_g[gi] + wt / dt;
        out[BATCH * HDIM + gi] = newc;            // new_c
        out[gi] = g_o[gi] * tanhf(newc);          // new_g
    }
}

// ---------------- launch --------------------------------------------------------
extern "C" void kernel_launch(void* const* d_in, const int* in_sizes, int n_in,
                              void* d_out, int out_size)
{
    const float* g   = (const float*)d_in[0];
    const float* c_g = (const float*)d_in[1];
    const float* h   = (const float*)d_in[2];
    const float* c   = (const float*)d_in[3];
    const float* W_w = (const float*)d_in[4];
    const float* w_w = (const float*)d_in[5];
    const float* U_w = (const float*)d_in[6];
    const float* U_b = (const float*)d_in[7];
    const float* u_w = (const float*)d_in[8];
    const float* u_b = (const float*)d_in[9];
    float* out = (float*)d_out;

    (void)in_sizes; (void)n_in; (void)out_size;

    k_prep<<<128, 256>>>(h);
    k_convw<<<512, 256>>>(u_w);
    k_fo<<<dim3(12, 8), 256>>>(g, W_w, U_w, w_w);
    k_fo_fin<<<768, 256>>>(U_b);

    static int smem_set = 0;
    if (!smem_set) {
        cudaFuncSetAttribute(k_main, cudaFuncAttributeMaxDynamicSharedMemorySize,
                             K3_SMEM_BYTES);
        smem_set = 1;
    }
    k_main<<<dim3(8, 128), 512, K3_SMEM_BYTES>>>(c, u_b, c_g, out);
}

// round 6
// speedup vs baseline: 4.4136x; 1.1205x over previous
#include <cuda_runtime.h>
#include <cuda_fp16.h>
#include <math.h>
#include <stdint.h>

#define BATCH 128
#define WDIM  512
#define HDIM  512
#define WH    (WDIM * HDIM)
#define NOUT  1536
#define K2_SPLITS 16

// ---------------- scratch (device globals: allocation-free rule) -------------
__device__ __align__(16) float  g_havg[BATCH * HDIM];
__device__ __align__(16) float  g_f[BATCH * HDIM];
__device__ __align__(16) float  g_o[BATCH * HDIM];
__device__ __align__(16) float  g_a[BATCH * HDIM];
__device__ __align__(16) float  g_part[K2_SPLITS * BATCH * NOUT];
__device__ __align__(16) __half g_h16[BATCH * WH];        // fp16 copy of h
__device__ __align__(16) __half g_uw16[HDIM * HDIM];      // fp16 copy of u_w

// ---------------- fast math ------------------------------------------------------
__device__ __forceinline__ float fast_exp(float x)
{
    float y = x * 1.44269504089f;
    y = fminf(fmaxf(y, -125.0f), 125.0f);
    float z = y + 12582912.0f;
    int   n = __float_as_int(z) - 0x4B400000;
    float f = y - (z - 12582912.0f);
    float t = f * 0.69314718056f;
    float p = 0.0013888889f;
    p = fmaf(p, t, 0.0083333333f);
    p = fmaf(p, t, 0.0416666667f);
    p = fmaf(p, t, 0.1666666667f);
    p = fmaf(p, t, 0.5f);
    p = fmaf(p, t, 1.0f);
    p = fmaf(p, t, 1.0f);
    return __int_as_float(__float_as_int(p) + (n << 23));
}
__device__ __forceinline__ float fast_rcp(float d)
{
    float r = __int_as_float(0x7EF311C3 - __float_as_int(d));
    r = r * (2.0f - d * r);
    r = r * (2.0f - d * r);
    r = r * (2.0f - d * r);
    return r;
}
__device__ __forceinline__ float tanh_mufu(float x)
{
    float r;
    asm("tanh.approx.f32 %0, %1;" : "=f"(r) : "f"(x));
    return r;
}
__device__ __forceinline__ float ex2_mufu(float x)
{
    float r;
    asm("ex2.approx.f32 %0, %1;" : "=f"(r) : "f"(x));
    return r;
}

// ---------------- mma / ldmatrix / cp.async helpers ------------------------------
__device__ __forceinline__ void mma_f16(float* d, const uint32_t* a, const uint32_t* b)
{
    asm volatile(
        "mma.sync.aligned.m16n8k16.row.col.f32.f16.f16.f32 "
        "{%0,%1,%2,%3}, {%4,%5,%6,%7}, {%8,%9}, {%0,%1,%2,%3};"
        : "+f"(d[0]), "+f"(d[1]), "+f"(d[2]), "+f"(d[3])
        : "r"(a[0]), "r"(a[1]), "r"(a[2]), "r"(a[3]),
          "r"(b[0]), "r"(b[1]));
}
__device__ __forceinline__ void ldsm_x4(uint32_t* r, uint32_t addr)
{
    asm volatile("ldmatrix.sync.aligned.m8n8.x4.shared.b16 {%0,%1,%2,%3}, [%4];"
                 : "=r"(r[0]), "=r"(r[1]), "=r"(r[2]), "=r"(r[3]) : "r"(addr));
}
__device__ __forceinline__ void ldsm_x2(uint32_t* r, uint32_t addr)
{
    asm volatile("ldmatrix.sync.aligned.m8n8.x2.shared.b16 {%0,%1}, [%2];"
                 : "=r"(r[0]), "=r"(r[1]) : "r"(addr));
}
__device__ __forceinline__ void cp16(uint32_t saddr, const void* g)
{
    asm volatile("cp.async.cg.shared.global [%0], [%1], 16;" :: "r"(saddr), "l"(g));
}
__device__ __forceinline__ void cp_commit()
{
    asm volatile("cp.async.commit_group;" ::: "memory");
}
template<int N> __device__ __forceinline__ void cp_wait()
{
    asm volatile("cp.async.wait_group %0;" :: "n"(N) : "memory");
}

// ---------------- K0: h -> fp16 + h_avg (single pass over h) ---------------------
__global__ void k_prep(const float* __restrict__ h)
{
    int idx = blockIdx.x * blockDim.x + threadIdx.x;   // (b, jpair)
    int b  = idx >> 8;
    int jp = idx & 255;
    const float2* p = (const float2*)(h + (size_t)b * WH) + jp;
    __half2* q = (__half2*)(g_h16 + (size_t)b * WH) + jp;
    float s0 = 0.f, s1 = 0.f;
#pragma unroll 4
    for (int w = 0; w < WDIM; ++w) {
        float2 v = p[(size_t)w * (HDIM / 2)];
        s0 += v.x; s1 += v.y;
        q[(size_t)w * (HDIM / 2)] = __floats2half2_rn(v.x, v.y);
    }
    g_havg[b * HDIM + jp * 2]     = s0 * (1.0f / WDIM);
    g_havg[b * HDIM + jp * 2 + 1] = s1 * (1.0f / WDIM);
}

// ---------------- K0b: u_w -> fp16 -----------------------------------------------
__global__ void k_convw(const float* __restrict__ u_w)
{
    int idx = blockIdx.x * blockDim.x + threadIdx.x;
    float2 v = ((const float2*)u_w)[idx];
    ((__half2*)g_uw16)[idx] = __floats2half2_rn(v.x, v.y);
}

// ---------------- K2: split-K fp32 GEMM for [fo | a] ------------------------------
__global__ void __launch_bounds__(256)
k_fo(const float* __restrict__ g, const float* __restrict__ W_w,
     const float* __restrict__ U_w, const float* __restrict__ w_w)
{
    __shared__ __align__(16) float As[16 * 132];
    __shared__ __align__(16) float Bs[16 * 132];

    int nt  = blockIdx.x;
    int ks  = blockIdx.y;          // 0..15, 64-wide K slice
    int tid = threadIdx.x;
    int tx  = tid & 15;
    int ty  = tid >> 4;

    float acc[8][8];
#pragma unroll
    for (int r = 0; r < 8; ++r)
#pragma unroll
        for (int s = 0; s < 8; ++s) acc[r][s] = 0.f;

    const int kbase = ks * 64;
    const int q  = tid & 3;
    const int lr = tid >> 2;

    for (int kk = 0; kk < 64; kk += 16) {
#pragma unroll
        for (int p = 0; p < 2; ++p) {
            int b  = p * 64 + lr;
            int kg = kbase + kk + q * 4;
            float4 v;
            if (kg < 512) v = *(const float4*)(g + b * 512 + kg);
            else          v = *(const float4*)(&g_havg[b * 512 + (kg - 512)]);
            float* dst = &As[(q * 4) * 132 + b];
            dst[0] = v.x; dst[132] = v.y; dst[2*132] = v.z; dst[3*132] = v.w;
        }
#pragma unroll
        for (int p = 0; p < 2; ++p) {
            int jj = p * 64 + lr;
            int j  = nt * 128 + jj;
            int kg = kbase + kk + q * 4;
            float4 v;
            if (j < 1024) {
                if (kg < 512) v = *(const float4*)(W_w + j * 512 + kg);
                else          v = *(const float4*)(U_w + j * 512 + (kg - 512));
            } else {
                if (kg < 512) v = *(const float4*)(w_w + (j - 1024) * 512 + kg);
                else          v = make_float4(0.f, 0.f, 0.f, 0.f);
            }
            float* dst = &Bs[(q * 4) * 132 + jj];
            dst[0] = v.x; dst[132] = v.y; dst[2*132] = v.z; dst[3*132] = v.w;
        }
        __syncthreads();

#pragma unroll
        for (int kc = 0; kc < 16; ++kc) {
            float4 a0 = *(const float4*)&As[kc * 132 + ty * 8];
            float4 a1 = *(const float4*)&As[kc * 132 + ty * 8 + 4];
            float4 b0 = *(const float4*)&Bs[kc * 132 + tx * 8];
            float4 b1 = *(const float4*)&Bs[kc * 132 + tx * 8 + 4];
            float av[8] = {a0.x, a0.y, a0.z, a0.w, a1.x, a1.y, a1.z, a1.w};
            float bv[8] = {b0.x, b0.y, b0.z, b0.w, b1.x, b1.y, b1.z, b1.w};
#pragma unroll
            for (int r = 0; r < 8; ++r)
#pragma unroll
                for (int s = 0; s < 8; ++s) acc[r][s] += av[r] * bv[s];
        }
        __syncthreads();
    }

#pragma unroll
    for (int r = 0; r < 8; ++r) {
        int bb = ty * 8 + r;
        float* dst = &g_part[(ks * 128 + bb) * NOUT + nt * 128 + tx * 8];
        *(float4*)dst       = make_float4(acc[r][0], acc[r][1], acc[r][2], acc[r][3]);
        *(float4*)(dst + 4) = make_float4(acc[r][4], acc[r][5], acc[r][6], acc[r][7]);
    }
}

// ---------------- K2b --------------------------------------------------------------
__global__ void k_fo_fin(const float* __restrict__ U_b)
{
    int idx = blockIdx.x * blockDim.x + threadIdx.x;
    int b = idx / NOUT;
    int j = idx - b * NOUT;
    float s = 0.f;
#pragma unroll
    for (int ks = 0; ks < K2_SPLITS; ++ks)
        s += g_part[(ks * 128 + b) * NOUT + j];
    if (j < 1024) {
        s += U_b[j];
        s = fast_rcp(1.f + fast_exp(-s));
        if (j < 512) g_f[b * 512 + j] = s;
        else         g_o[b * 512 + (j - 512)] = s;
    } else {
        g_a[b * 512 + (j - 1024)] = s;
    }
}

// ---------------- K3: fp16 mma + MUFU softmax epilogue (S fp16) -------------------
#define KCH     64
#define NCHUNK  8
// float offsets in dynamic smem
#define OFF_ADD_F  0               // 64 floats
#define OFF_R1_F   64              // 16 segs x 64 cols
#define OFF_R2_F   1088
#define HDR_FLOATS 2112            // 8448 bytes
#define SM_STAGE_B 8448            // stages: A 64KB + B 8KB, x2
#define A_BYTES    65536
#define STAGE_BYTES 73728
#define S2_STRIDE  33              // half2 words per row
#define K3_SMEM_BYTES (SM_STAGE_B + 2 * STAGE_BYTES)   // 155904

__global__ void __launch_bounds__(512, 1)
k_main(const float* __restrict__ c, const float* __restrict__ u_b,
       const float* __restrict__ c_g, float* __restrict__ out)
{
    extern __shared__ __align__(128) float sm[];
    const uint32_t smb = (uint32_t)__cvta_generic_to_shared(sm);

    const int b    = blockIdx.y;
    const int ht0  = blockIdx.x * 64;
    const int tid  = threadIdx.x;
    const int wid  = tid >> 5;
    const int lane = tid & 31;
    const int wm   = wid >> 1;
    const int wn   = wid & 1;
    const int g4   = lane >> 2;
    const int t4   = lane & 3;

    const __half* hb = g_h16 + (size_t)b * WH;

    if (tid < 64)
        sm[OFF_ADD_F + tid] = g_a[b * HDIM + ht0 + tid] + u_b[ht0 + tid];

    const int arow = tid >> 3;        // 0..63
    const int aq   = tid & 7;

    auto load_chunk = [&](int ch, int st) {
        const uint32_t sa = smb + SM_STAGE_B + (uint32_t)st * STAGE_BYTES;
        const __half* gA = hb + ch * KCH + aq * 8;
#pragma unroll
        for (int p = 0; p < 8; ++p) {
            int row = arow + p * 64;
            cp16(sa + (uint32_t)(row * 128 + ((aq ^ (row & 7)) << 4)),
                 gA + (size_t)row * HDIM);
        }
        const __half* gB = g_uw16 + (size_t)(ht0 + arow) * HDIM + ch * KCH + aq * 8;
        cp16(sa + A_BYTES + (uint32_t)(arow * 128 + ((aq ^ (arow & 7)) << 4)), gB);
        cp_commit();
    };

    const int lane15 = lane & 15;
    const int laneQA = lane >> 4;
    const int laneB7 = lane & 7;
    const int laneQB = (lane >> 3) & 1;

    uint32_t aBase[4], aRL[4];
#pragma unroll
    for (int tm = 0; tm < 4; ++tm) {
        int row = wm * 64 + tm * 16 + lane15;
        aRL[tm]   = row & 7;
        aBase[tm] = smb + SM_STAGE_B + (uint32_t)(row * 128);
    }
    uint32_t bBase[4], bRL[4];
#pragma unroll
    for (int tn = 0; tn < 4; ++tn) {
        int row = wn * 32 + tn * 8 + laneB7;
        bRL[tn]   = row & 7;
        bBase[tn] = smb + SM_STAGE_B + A_BYTES + (uint32_t)(row * 128);
    }

    float acc[4][4][4];
#pragma unroll
    for (int i = 0; i < 4; ++i)
#pragma unroll
        for (int j = 0; j < 4; ++j)
#pragma unroll
            for (int r = 0; r < 4; ++r) acc[i][j][r] = 0.f;

    load_chunk(0, 0);
    load_chunk(1, 1);

    for (int ch = 0; ch < NCHUNK; ++ch) {
        const int st = ch & 1;
        if (ch == NCHUNK - 1) cp_wait<0>(); else cp_wait<1>();
        __syncthreads();

        const uint32_t off = (uint32_t)st * STAGE_BYTES;
#pragma unroll
        for (int ks = 0; ks < 4; ++ks) {
            const uint32_t qb = (uint32_t)(ks * 2);
            uint32_t af[4][4], bf[4][2];
#pragma unroll
            for (int tm = 0; tm < 4; ++tm)
                ldsm_x4(af[tm], aBase[tm] + off + (((qb + laneQA) ^ aRL[tm]) << 4));
#pragma unroll
            for (int tn = 0; tn < 4; ++tn)
                ldsm_x2(bf[tn], bBase[tn] + off + (((qb + laneQB) ^ bRL[tn]) << 4));
#pragma unroll
            for (int tm = 0; tm < 4; ++tm)
#pragma unroll
                for (int tn = 0; tn < 4; ++tn)
                    mma_f16(acc[tm][tn], af[tm], bf[tn]);
        }
        __syncthreads();
        if (ch + 2 < NCHUNK) load_chunk(ch + 2, st);
    }

    // ---- epilogue: exp(sigmoid(x)) ∝ exp2(K * tanh(x/2)); sqrt(e) cancels -------
    // S stored as half2 in stage-0 region (dead after mainloop).
    __half2* S2 = (__half2*)(sm + SM_STAGE_B / 4);
    const float KE = 0.72134752f;     // 0.5 * log2(e)
#pragma unroll
    for (int tm = 0; tm < 4; ++tm) {
#pragma unroll
        for (int tn = 0; tn < 4; ++tn) {
            int colb = wn * 32 + tn * 8 + t4 * 2;
            float add0 = sm[OFF_ADD_F + colb];
            float add1 = sm[OFF_ADD_F + colb + 1];
#pragma unroll
            for (int r = 0; r < 2; ++r) {
                int w = wm * 64 + tm * 16 + g4 + r * 8;
                float x0 = acc[tm][tn][r * 2 + 0] + add0;
                float x1 = acc[tm][tn][r * 2 + 1] + add1;
                float s0 = ex2_mufu(KE * tanh_mufu(0.5f * x0));
                float s1 = ex2_mufu(KE * tanh_mufu(0.5f * x1));
                S2[w * S2_STRIDE + (colb >> 1)] = __floats2half2_rn(s0, s1);
            }
        }
    }
    __syncthreads();

    // ---- fused: softmax denominator + weighted-c numerator (packed pairs) -------
    const int colp = tid & 31;        // column pair
    const int seg  = tid >> 5;        // 16 segments x 32 w
    const float* cbase = c + (size_t)b * WH + ht0 + colp * 2;
    float dsx = 0.f, dsy = 0.f, wsx = 0.f, wsy = 0.f;
#pragma unroll 4
    for (int ww = 0; ww < 32; ++ww) {
        int w = seg * 32 + ww;
        float2 e  = __half22float2(S2[w * S2_STRIDE + colp]);
        float2 cv = *(const float2*)(cbase + (size_t)w * HDIM);
        dsx += e.x; dsy += e.y;
        wsx += e.x * cv.x; wsy += e.y * cv.y;
    }
    *(float2*)&sm[OFF_R1_F + seg * 64 + colp * 2] = make_float2(dsx, dsy);
    *(float2*)&sm[OFF_R2_F + seg * 64 + colp * 2] = make_float2(wsx, wsy);
    __syncthreads();

    if (tid < 64) {
        float dt = 0.f, wt = 0.f;
#pragma unroll
        for (int s2 = 0; s2 < 16; ++s2) {
            dt += sm[OFF_R1_F + s2 * 64 + tid];
            wt += sm[OFF_R2_F + s2 * 64 + tid];
        }
        int gi = b * HDIM + ht0 + tid;
        float newc = g_f[gi] * c_g[gi] + wt / dt;
        out[BATCH * HDIM + gi] = newc;            // new_c
        out[gi] = g_o[gi] * tanhf(newc);          // new_g
    }
}

// ---------------- launch --------------------------------------------------------
extern "C" void kernel_launch(void* const* d_in, const int* in_sizes, int n_in,
                              void* d_out, int out_size)
{
    const float* g   = (const float*)d_in[0];
    const float* c_g = (const float*)d_in[1];
    const float* h   = (const float*)d_in[2];
    const float* c   = (const float*)d_in[3];
    const float* W_w = (const float*)d_in[4];
    const float* w_w = (const float*)d_in[5];
    const float* U_w = (const float*)d_in[6];
    const float* U_b = (const float*)d_in[7];
    const float* u_w = (const float*)d_in[8];
    const float* u_b = (const float*)d_in[9];
    float* out = (float*)d_out;

    (void)in_sizes; (void)n_in; (void)out_size;

    k_prep<<<128, 256>>>(h);
    k_convw<<<512, 256>>>(u_w);
    k_fo<<<dim3(12, 16), 256>>>(g, W_w, U_w, w_w);
    k_fo_fin<<<768, 256>>>(U_b);

    static int smem_set = 0;
    if (!smem_set) {
        cudaFuncSetAttribute(k_main, cudaFuncAttributeMaxDynamicSharedMemorySize,
                             K3_SMEM_BYTES);
        smem_set = 1;
    }
    k_main<<<dim3(8, 128), 512, K3_SMEM_BYTES>>>(c, u_b, c_g, out);
}

// round 7
// speedup vs baseline: 4.4152x; 1.0004x over previous
#include <cuda_runtime.h>
#include <cuda_fp16.h>
#include <math.h>
#include <stdint.h>

#define BATCH 128
#define WDIM  512
#define HDIM  512
#define WH    (WDIM * HDIM)
#define NOUT  1536
#define K2_SPLITS 16

// ---------------- scratch (device globals: allocation-free rule) -------------
__device__ __align__(16) float  g_havg[BATCH * HDIM];
__device__ __align__(16) float  g_f[BATCH * HDIM];
__device__ __align__(16) float  g_o[BATCH * HDIM];
__device__ __align__(16) float  g_a[BATCH * HDIM];
__device__ __align__(16) float  g_part[K2_SPLITS * BATCH * NOUT];
__device__ __align__(16) __half g_h16[BATCH * WH];        // fp16 copy of h
__device__ __align__(16) __half g_uw16[HDIM * HDIM];      // fp16 copy of u_w

// ---------------- fast math ------------------------------------------------------
__device__ __forceinline__ float fast_exp(float x)
{
    float y = x * 1.44269504089f;
    y = fminf(fmaxf(y, -125.0f), 125.0f);
    float z = y + 12582912.0f;
    int   n = __float_as_int(z) - 0x4B400000;
    float f = y - (z - 12582912.0f);
    float t = f * 0.69314718056f;
    float p = 0.0013888889f;
    p = fmaf(p, t, 0.0083333333f);
    p = fmaf(p, t, 0.0416666667f);
    p = fmaf(p, t, 0.1666666667f);
    p = fmaf(p, t, 0.5f);
    p = fmaf(p, t, 1.0f);
    p = fmaf(p, t, 1.0f);
    return __int_as_float(__float_as_int(p) + (n << 23));
}
__device__ __forceinline__ float fast_rcp(float d)
{
    float r = __int_as_float(0x7EF311C3 - __float_as_int(d));
    r = r * (2.0f - d * r);
    r = r * (2.0f - d * r);
    r = r * (2.0f - d * r);
    return r;
}
__device__ __forceinline__ float tanh_mufu(float x)
{
    float r;
    asm("tanh.approx.f32 %0, %1;" : "=f"(r) : "f"(x));
    return r;
}
__device__ __forceinline__ float ex2_mufu(float x)
{
    float r;
    asm("ex2.approx.f32 %0, %1;" : "=f"(r) : "f"(x));
    return r;
}

// ---------------- mma / ldmatrix / cp.async helpers ------------------------------
__device__ __forceinline__ void mma_f16(float* d, const uint32_t* a, const uint32_t* b)
{
    asm volatile(
        "mma.sync.aligned.m16n8k16.row.col.f32.f16.f16.f32 "
        "{%0,%1,%2,%3}, {%4,%5,%6,%7}, {%8,%9}, {%0,%1,%2,%3};"
        : "+f"(d[0]), "+f"(d[1]), "+f"(d[2]), "+f"(d[3])
        : "r"(a[0]), "r"(a[1]), "r"(a[2]), "r"(a[3]),
          "r"(b[0]), "r"(b[1]));
}
__device__ __forceinline__ void ldsm_x4(uint32_t* r, uint32_t addr)
{
    asm volatile("ldmatrix.sync.aligned.m8n8.x4.shared.b16 {%0,%1,%2,%3}, [%4];"
                 : "=r"(r[0]), "=r"(r[1]), "=r"(r[2]), "=r"(r[3]) : "r"(addr));
}
__device__ __forceinline__ void cp16(uint32_t saddr, const void* g)
{
    asm volatile("cp.async.cg.shared.global [%0], [%1], 16;" :: "r"(saddr), "l"(g));
}
__device__ __forceinline__ void cp_commit()
{
    asm volatile("cp.async.commit_group;" ::: "memory");
}
template<int N> __device__ __forceinline__ void cp_wait()
{
    asm volatile("cp.async.wait_group %0;" :: "n"(N) : "memory");
}

// ---------------- K0: h -> fp16 + h_avg, and u_w -> fp16 (fused) -----------------
__global__ void k_prep(const float* __restrict__ h, const float* __restrict__ u_w)
{
    int gb  = blockIdx.x;
    int tid = threadIdx.x;
    if (gb < 128) {
        int b  = gb;
        int jp = tid;                 // 0..255 column pair
        const float2* p = (const float2*)(h + (size_t)b * WH) + jp;
        __half2* q = (__half2*)(g_h16 + (size_t)b * WH) + jp;
        float s0 = 0.f, s1 = 0.f;
#pragma unroll 4
        for (int w = 0; w < WDIM; ++w) {
            float2 v = p[(size_t)w * (HDIM / 2)];
            s0 += v.x; s1 += v.y;
            q[(size_t)w * (HDIM / 2)] = __floats2half2_rn(v.x, v.y);
        }
        g_havg[b * HDIM + jp * 2]     = s0 * (1.0f / WDIM);
        g_havg[b * HDIM + jp * 2 + 1] = s1 * (1.0f / WDIM);
    } else {
        // u_w conversion: 32 blocks x 256 threads, 8 float4 (=2 half2x2) each
        int t = (gb - 128) * 256 + tid;         // 0..8191
#pragma unroll
        for (int i = 0; i < 8; ++i) {
            int idx = t + i * 8192;             // float4 index, 65536 total
            float4 v = ((const float4*)u_w)[idx];
            __half2 h0 = __floats2half2_rn(v.x, v.y);
            __half2 h1 = __floats2half2_rn(v.z, v.w);
            ((__half2*)g_uw16)[idx * 2]     = h0;
            ((__half2*)g_uw16)[idx * 2 + 1] = h1;
        }
    }
}

// ---------------- K2: split-K fp32 GEMM for [fo | a] ------------------------------
__global__ void __launch_bounds__(256)
k_fo(const float* __restrict__ g, const float* __restrict__ W_w,
     const float* __restrict__ U_w, const float* __restrict__ w_w)
{
    __shared__ __align__(16) float As[16 * 132];
    __shared__ __align__(16) float Bs[16 * 132];

    int nt  = blockIdx.x;
    int ks  = blockIdx.y;          // 0..15, 64-wide K slice
    int tid = threadIdx.x;
    int tx  = tid & 15;
    int ty  = tid >> 4;

    float acc[8][8];
#pragma unroll
    for (int r = 0; r < 8; ++r)
#pragma unroll
        for (int s = 0; s < 8; ++s) acc[r][s] = 0.f;

    const int kbase = ks * 64;
    const int q  = tid & 3;
    const int lr = tid >> 2;

    for (int kk = 0; kk < 64; kk += 16) {
#pragma unroll
        for (int p = 0; p < 2; ++p) {
            int b  = p * 64 + lr;
            int kg = kbase + kk + q * 4;
            float4 v;
            if (kg < 512) v = *(const float4*)(g + b * 512 + kg);
            else          v = *(const float4*)(&g_havg[b * 512 + (kg - 512)]);
            float* dst = &As[(q * 4) * 132 + b];
            dst[0] = v.x; dst[132] = v.y; dst[2*132] = v.z; dst[3*132] = v.w;
        }
#pragma unroll
        for (int p = 0; p < 2; ++p) {
            int jj = p * 64 + lr;
            int j  = nt * 128 + jj;
            int kg = kbase + kk + q * 4;
            float4 v;
            if (j < 1024) {
                if (kg < 512) v = *(const float4*)(W_w + j * 512 + kg);
                else          v = *(const float4*)(U_w + j * 512 + (kg - 512));
            } else {
                if (kg < 512) v = *(const float4*)(w_w + (j - 1024) * 512 + kg);
                else          v = make_float4(0.f, 0.f, 0.f, 0.f);
            }
            float* dst = &Bs[(q * 4) * 132 + jj];
            dst[0] = v.x; dst[132] = v.y; dst[2*132] = v.z; dst[3*132] = v.w;
        }
        __syncthreads();

#pragma unroll
        for (int kc = 0; kc < 16; ++kc) {
            float4 a0 = *(const float4*)&As[kc * 132 + ty * 8];
            float4 a1 = *(const float4*)&As[kc * 132 + ty * 8 + 4];
            float4 b0 = *(const float4*)&Bs[kc * 132 + tx * 8];
            float4 b1 = *(const float4*)&Bs[kc * 132 + tx * 8 + 4];
            float av[8] = {a0.x, a0.y, a0.z, a0.w, a1.x, a1.y, a1.z, a1.w};
            float bv[8] = {b0.x, b0.y, b0.z, b0.w, b1.x, b1.y, b1.z, b1.w};
#pragma unroll
            for (int r = 0; r < 8; ++r)
#pragma unroll
                for (int s = 0; s < 8; ++s) acc[r][s] += av[r] * bv[s];
        }
        __syncthreads();
    }

#pragma unroll
    for (int r = 0; r < 8; ++r) {
        int bb = ty * 8 + r;
        float* dst = &g_part[(ks * 128 + bb) * NOUT + nt * 128 + tx * 8];
        *(float4*)dst       = make_float4(acc[r][0], acc[r][1], acc[r][2], acc[r][3]);
        *(float4*)(dst + 4) = make_float4(acc[r][4], acc[r][5], acc[r][6], acc[r][7]);
    }
}

// ---------------- K2b: vectorized reduce + activation -----------------------------
__global__ void k_fo_fin(const float* __restrict__ U_b)
{
    int idx = blockIdx.x * blockDim.x + threadIdx.x;   // 0..49151 (j quads)
    int b  = idx / (NOUT / 4);
    int j4 = idx - b * (NOUT / 4);
    int j  = j4 * 4;
    float4 s = make_float4(0.f, 0.f, 0.f, 0.f);
#pragma unroll
    for (int ks = 0; ks < K2_SPLITS; ++ks) {
        float4 v = *(const float4*)&g_part[(ks * 128 + b) * NOUT + j];
        s.x += v.x; s.y += v.y; s.z += v.z; s.w += v.w;
    }
    if (j < 1024) {
        float4 ub = *(const float4*)&U_b[j];
        s.x = fast_rcp(1.f + fast_exp(-(s.x + ub.x)));
        s.y = fast_rcp(1.f + fast_exp(-(s.y + ub.y)));
        s.z = fast_rcp(1.f + fast_exp(-(s.z + ub.z)));
        s.w = fast_rcp(1.f + fast_exp(-(s.w + ub.w)));
        if (j < 512) *(float4*)&g_f[b * 512 + j]         = s;
        else         *(float4*)&g_o[b * 512 + (j - 512)] = s;
    } else {
        *(float4*)&g_a[b * 512 + (j - 1024)] = s;
    }
}

// ---------------- K3: fp16 mma, 3-stage cp.async, 1 barrier/chunk -----------------
#define KCH     64
#define NCHUNK  8
#define NSTAGE  3
// float offsets in dynamic smem
#define OFF_ADD_F  0               // 64 floats
#define OFF_R1_F   64              // 16 segs x 64 cols
#define OFF_R2_F   1088
#define SM_STAGE_B 8448            // stages: A 64KB + B 8KB, x3
#define A_BYTES    65536
#define STAGE_BYTES 73728
#define S2_STRIDE  33              // half2 words per row
#define K3_SMEM_BYTES (SM_STAGE_B + NSTAGE * STAGE_BYTES)   // 229632

__global__ void __launch_bounds__(512, 1)
k_main(const float* __restrict__ c, const float* __restrict__ u_b,
       const float* __restrict__ c_g, float* __restrict__ out)
{
    extern __shared__ __align__(128) float sm[];
    const uint32_t smb = (uint32_t)__cvta_generic_to_shared(sm);

    const int b    = blockIdx.y;
    const int ht0  = blockIdx.x * 64;
    const int tid  = threadIdx.x;
    const int wid  = tid >> 5;
    const int lane = tid & 31;
    const int wm   = wid >> 1;
    const int wn   = wid & 1;
    const int g4   = lane >> 2;
    const int t4   = lane & 3;

    const __half* hb = g_h16 + (size_t)b * WH;

    if (tid < 64)
        sm[OFF_ADD_F + tid] = g_a[b * HDIM + ht0 + tid] + u_b[ht0 + tid];

    const int arow = tid >> 3;        // 0..63
    const int aq   = tid & 7;

    auto load_chunk = [&](int ch, int st) {
        const uint32_t sa = smb + SM_STAGE_B + (uint32_t)st * STAGE_BYTES;
        const __half* gA = hb + ch * KCH + aq * 8;
#pragma unroll
        for (int p = 0; p < 8; ++p) {
            int row = arow + p * 64;
            cp16(sa + (uint32_t)(row * 128 + ((aq ^ (row & 7)) << 4)),
                 gA + (size_t)row * HDIM);
        }
        const __half* gB = g_uw16 + (size_t)(ht0 + arow) * HDIM + ch * KCH + aq * 8;
        cp16(sa + A_BYTES + (uint32_t)(arow * 128 + ((aq ^ (arow & 7)) << 4)), gB);
        cp_commit();
    };

    // ---- ldmatrix per-lane bases ----
    const int lane15 = lane & 15;
    const int laneQA = lane >> 4;          // A x4: lanes 16-31 -> next k-quad
    const int laneQB = (lane >> 3) & 1;    // B x4: quad select within 16-lane half

    uint32_t aBase[4], aRL[4];
#pragma unroll
    for (int tm = 0; tm < 4; ++tm) {
        int row = wm * 64 + tm * 16 + lane15;
        aRL[tm]   = row & 7;
        aBase[tm] = smb + SM_STAGE_B + (uint32_t)(row * 128);
    }
    // B x4: pair p covers tn=2p,2p+1; row = wn*32 + p*16 + ((lane>>4)<<3) + (lane&7)
    uint32_t bBase[2], bRL[2];
#pragma unroll
    for (int p = 0; p < 2; ++p) {
        int row = wn * 32 + p * 16 + ((lane >> 4) << 3) + (lane & 7);
        bRL[p]   = row & 7;
        bBase[p] = smb + SM_STAGE_B + A_BYTES + (uint32_t)(row * 128);
    }

    float acc[4][4][4];
#pragma unroll
    for (int i = 0; i < 4; ++i)
#pragma unroll
        for (int j = 0; j < 4; ++j)
#pragma unroll
            for (int r = 0; r < 4; ++r) acc[i][j][r] = 0.f;

    // ---- 3-stage pipeline, ONE barrier per chunk ----
    load_chunk(0, 0);
    load_chunk(1, 1);

    int st = 0;
    for (int ch = 0; ch < NCHUNK; ++ch) {
        if (ch == NCHUNK - 1) cp_wait<0>(); else cp_wait<1>();
        __syncthreads();

        // prefetch chunk ch+2 into stage (st+2)%3 — safe: that stage's last
        // readers (chunk ch-1) all passed the barrier above.
        if (ch + 2 < NCHUNK) {
            int st2 = st + 2; if (st2 >= NSTAGE) st2 -= NSTAGE;
            load_chunk(ch + 2, st2);
        }

        const uint32_t off = (uint32_t)st * STAGE_BYTES;
#pragma unroll
        for (int ks = 0; ks < 4; ++ks) {
            const uint32_t qb = (uint32_t)(ks * 2);
            uint32_t af[4][4], bf[4][2];
#pragma unroll
            for (int tm = 0; tm < 4; ++tm)
                ldsm_x4(af[tm], aBase[tm] + off + (((qb + laneQA) ^ aRL[tm]) << 4));
#pragma unroll
            for (int p = 0; p < 2; ++p) {
                uint32_t tmp[4];
                ldsm_x4(tmp, bBase[p] + off + (((qb + laneQB) ^ bRL[p]) << 4));
                bf[2 * p][0] = tmp[0]; bf[2 * p][1] = tmp[1];
                bf[2 * p + 1][0] = tmp[2]; bf[2 * p + 1][1] = tmp[3];
            }
#pragma unroll
            for (int tm = 0; tm < 4; ++tm)
#pragma unroll
                for (int tn = 0; tn < 4; ++tn)
                    mma_f16(acc[tm][tn], af[tm], bf[tn]);
        }
        if (++st >= NSTAGE) st = 0;
    }
    __syncthreads();   // stage region about to be reused as S

    // ---- epilogue: exp(sigmoid(x)) ∝ exp2(K * tanh(x/2)); sqrt(e) cancels -------
    __half2* S2 = (__half2*)(sm + SM_STAGE_B / 4);
    const float KE = 0.72134752f;     // 0.5 * log2(e)
#pragma unroll
    for (int tm = 0; tm < 4; ++tm) {
#pragma unroll
        for (int tn = 0; tn < 4; ++tn) {
            int colb = wn * 32 + tn * 8 + t4 * 2;
            float add0 = sm[OFF_ADD_F + colb];
            float add1 = sm[OFF_ADD_F + colb + 1];
#pragma unroll
            for (int r = 0; r < 2; ++r) {
                int w = wm * 64 + tm * 16 + g4 + r * 8;
                float x0 = acc[tm][tn][r * 2 + 0] + add0;
                float x1 = acc[tm][tn][r * 2 + 1] + add1;
                float s0 = ex2_mufu(KE * tanh_mufu(0.5f * x0));
                float s1 = ex2_mufu(KE * tanh_mufu(0.5f * x1));
                S2[w * S2_STRIDE + (colb >> 1)] = __floats2half2_rn(s0, s1);
            }
        }
    }
    __syncthreads();

    // ---- fused: softmax denominator + weighted-c numerator (packed pairs) -------
    const int colp = tid & 31;        // column pair
    const int seg  = tid >> 5;        // 16 segments x 32 w
    const float* cbase = c + (size_t)b * WH + ht0 + colp * 2;
    float dsx = 0.f, dsy = 0.f, wsx = 0.f, wsy = 0.f;
#pragma unroll 4
    for (int ww = 0; ww < 32; ++ww) {
        int w = seg * 32 + ww;
        float2 e  = __half22float2(S2[w * S2_STRIDE + colp]);
        float2 cv = *(const float2*)(cbase + (size_t)w * HDIM);
        dsx += e.x; dsy += e.y;
        wsx += e.x * cv.x; wsy += e.y * cv.y;
    }
    *(float2*)&sm[OFF_R1_F + seg * 64 + colp * 2] = make_float2(dsx, dsy);
    *(float2*)&sm[OFF_R2_F + seg * 64 + colp * 2] = make_float2(wsx, wsy);
    __syncthreads();

    if (tid < 64) {
        float dt = 0.f, wt = 0.f;
#pragma unroll
        for (int s2 = 0; s2 < 16; ++s2) {
            dt += sm[OFF_R1_F + s2 * 64 + tid];
            wt += sm[OFF_R2_F + s2 * 64 + tid];
        }
        int gi = b * HDIM + ht0 + tid;
        float newc = g_f[gi] * c_g[gi] + wt / dt;
        out[BATCH * HDIM + gi] = newc;            // new_c
        out[gi] = g_o[gi] * tanhf(newc);          // new_g
    }
}

// ---------------- launch --------------------------------------------------------
extern "C" void kernel_launch(void* const* d_in, const int* in_sizes, int n_in,
                              void* d_out, int out_size)
{
    const float* g   = (const float*)d_in[0];
    const float* c_g = (const float*)d_in[1];
    const float* h   = (const float*)d_in[2];
    const float* c   = (const float*)d_in[3];
    const float* W_w = (const float*)d_in[4];
    const float* w_w = (const float*)d_in[5];
    const float* U_w = (const float*)d_in[6];
    const float* U_b = (const float*)d_in[7];
    const float* u_w = (const float*)d_in[8];
    const float* u_b = (const float*)d_in[9];
    float* out = (float*)d_out;

    (void)in_sizes; (void)n_in; (void)out_size;

    k_prep<<<160, 256>>>(h, u_w);
    k_fo<<<dim3(12, 16), 256>>>(g, W_w, U_w, w_w);
    k_fo_fin<<<192, 256>>>(U_b);

    static int smem_set = 0;
    if (!smem_set) {
        cudaFuncSetAttribute(k_main, cudaFuncAttributeMaxDynamicSharedMemorySize,
                             K3_SMEM_BYTES);
        smem_set = 1;
    }
    k_main<<<dim3(8, 128), 512, K3_SMEM_BYTES>>>(c, u_b, c_g, out);
}

// round 8
// speedup vs baseline: 6.5208x; 1.4769x over previous
#include <cuda_runtime.h>
#include <cuda_fp16.h>
#include <math.h>
#include <stdint.h>

#define BATCH 128
#define WDIM  512
#define HDIM  512
#define WH    (WDIM * HDIM)
#define NOUT  1536
#define K2_SPLITS 16

// ---------------- scratch (device globals: allocation-free rule) -------------
__device__ __align__(16) float  g_hpart[4 * BATCH * HDIM];   // partial W-sums of h
__device__ __align__(16) float  g_f[BATCH * HDIM];
__device__ __align__(16) float  g_o[BATCH * HDIM];
__device__ __align__(16) float  g_a[BATCH * HDIM];
__device__ __align__(16) float  g_part[K2_SPLITS * BATCH * NOUT];
__device__ __align__(16) float  g_red1[2 * BATCH * HDIM];    // softmax denom partials
__device__ __align__(16) float  g_red2[2 * BATCH * HDIM];    // weighted-c partials
__device__ __align__(16) __half g_h16[BATCH * WH];           // fp16 copy of h
__device__ __align__(16) __half g_uw16[HDIM * HDIM];         // fp16 copy of u_w

// ---------------- fast math ------------------------------------------------------
__device__ __forceinline__ float fast_exp(float x)
{
    float y = x * 1.44269504089f;
    y = fminf(fmaxf(y, -125.0f), 125.0f);
    float z = y + 12582912.0f;
    int   n = __float_as_int(z) - 0x4B400000;
    float f = y - (z - 12582912.0f);
    float t = f * 0.69314718056f;
    float p = 0.0013888889f;
    p = fmaf(p, t, 0.0083333333f);
    p = fmaf(p, t, 0.0416666667f);
    p = fmaf(p, t, 0.1666666667f);
    p = fmaf(p, t, 0.5f);
    p = fmaf(p, t, 1.0f);
    p = fmaf(p, t, 1.0f);
    return __int_as_float(__float_as_int(p) + (n << 23));
}
__device__ __forceinline__ float fast_rcp(float d)
{
    float r = __int_as_float(0x7EF311C3 - __float_as_int(d));
    r = r * (2.0f - d * r);
    r = r * (2.0f - d * r);
    r = r * (2.0f - d * r);
    return r;
}
__device__ __forceinline__ float tanh_mufu(float x)
{
    float r;
    asm("tanh.approx.f32 %0, %1;" : "=f"(r) : "f"(x));
    return r;
}
__device__ __forceinline__ float ex2_mufu(float x)
{
    float r;
    asm("ex2.approx.f32 %0, %1;" : "=f"(r) : "f"(x));
    return r;
}

// ---------------- mma / ldmatrix / cp.async helpers ------------------------------
__device__ __forceinline__ void mma_f16(float* d, const uint32_t* a, const uint32_t* b)
{
    asm volatile(
        "mma.sync.aligned.m16n8k16.row.col.f32.f16.f16.f32 "
        "{%0,%1,%2,%3}, {%4,%5,%6,%7}, {%8,%9}, {%0,%1,%2,%3};"
        : "+f"(d[0]), "+f"(d[1]), "+f"(d[2]), "+f"(d[3])
        : "r"(a[0]), "r"(a[1]), "r"(a[2]), "r"(a[3]),
          "r"(b[0]), "r"(b[1]));
}
__device__ __forceinline__ void ldsm_x4(uint32_t* r, uint32_t addr)
{
    asm volatile("ldmatrix.sync.aligned.m8n8.x4.shared.b16 {%0,%1,%2,%3}, [%4];"
                 : "=r"(r[0]), "=r"(r[1]), "=r"(r[2]), "=r"(r[3]) : "r"(addr));
}
__device__ __forceinline__ void cp16(uint32_t saddr, const void* g)
{
    asm volatile("cp.async.cg.shared.global [%0], [%1], 16;" :: "r"(saddr), "l"(g));
}
__device__ __forceinline__ void cp_commit()
{
    asm volatile("cp.async.commit_group;" ::: "memory");
}
template<int N> __device__ __forceinline__ void cp_wait()
{
    asm volatile("cp.async.wait_group %0;" :: "n"(N) : "memory");
}

// ---------------- K0: h -> fp16 + partial W sums; u_w -> fp16 ---------------------
__global__ void k_prep(const float* __restrict__ h, const float* __restrict__ u_w)
{
    int gb  = blockIdx.x;
    int tid = threadIdx.x;
    if (gb < 512) {
        int b  = gb >> 2;
        int ws = gb & 3;              // 128-row W slice
        int jp = tid;                 // 0..255 column pair
        const float2* p = (const float2*)(h + (size_t)b * WH +
                                          (size_t)ws * 128 * HDIM) + jp;
        __half2* q = (__half2*)(g_h16 + (size_t)b * WH +
                                (size_t)ws * 128 * HDIM) + jp;
        float s0 = 0.f, s1 = 0.f;
#pragma unroll 4
        for (int w = 0; w < 128; ++w) {
            float2 v = p[(size_t)w * (HDIM / 2)];
            s0 += v.x; s1 += v.y;
            q[(size_t)w * (HDIM / 2)] = __floats2half2_rn(v.x, v.y);
        }
        g_hpart[(ws * BATCH + b) * HDIM + jp * 2]     = s0;
        g_hpart[(ws * BATCH + b) * HDIM + jp * 2 + 1] = s1;
    } else {
        int t = (gb - 512) * 256 + tid;          // 0..8191
#pragma unroll
        for (int i = 0; i < 8; ++i) {
            int idx = t + i * 8192;              // float4 index, 65536 total
            float4 v = ((const float4*)u_w)[idx];
            ((__half2*)g_uw16)[idx * 2]     = __floats2half2_rn(v.x, v.y);
            ((__half2*)g_uw16)[idx * 2 + 1] = __floats2half2_rn(v.z, v.w);
        }
    }
}

// ---------------- K2: split-K fp32 GEMM for [fo | a] ------------------------------
__global__ void __launch_bounds__(256)
k_fo(const float* __restrict__ g, const float* __restrict__ W_w,
     const float* __restrict__ U_w, const float* __restrict__ w_w)
{
    __shared__ __align__(16) float As[16 * 132];
    __shared__ __align__(16) float Bs[16 * 132];

    int nt  = blockIdx.x;
    int ks  = blockIdx.y;          // 0..15, 64-wide K slice
    int tid = threadIdx.x;
    int tx  = tid & 15;
    int ty  = tid >> 4;

    float acc[8][8];
#pragma unroll
    for (int r = 0; r < 8; ++r)
#pragma unroll
        for (int s = 0; s < 8; ++s) acc[r][s] = 0.f;

    const int kbase = ks * 64;
    const int q  = tid & 3;
    const int lr = tid >> 2;

    for (int kk = 0; kk < 64; kk += 16) {
#pragma unroll
        for (int p = 0; p < 2; ++p) {
            int b  = p * 64 + lr;
            int kg = kbase + kk + q * 4;
            float4 v;
            if (kg < 512) {
                v = *(const float4*)(g + b * 512 + kg);
            } else {
                // h_avg = (sum of 4 W-slice partials) / 512
                float4 a4 = make_float4(0.f, 0.f, 0.f, 0.f);
#pragma unroll
                for (int s = 0; s < 4; ++s) {
                    float4 t = *(const float4*)&g_hpart[(s * BATCH + b) * HDIM +
                                                        (kg - 512)];
                    a4.x += t.x; a4.y += t.y; a4.z += t.z; a4.w += t.w;
                }
                const float inv = 1.0f / 512.0f;
                v = make_float4(a4.x * inv, a4.y * inv, a4.z * inv, a4.w * inv);
            }
            float* dst = &As[(q * 4) * 132 + b];
            dst[0] = v.x; dst[132] = v.y; dst[2*132] = v.z; dst[3*132] = v.w;
        }
#pragma unroll
        for (int p = 0; p < 2; ++p) {
            int jj = p * 64 + lr;
            int j  = nt * 128 + jj;
            int kg = kbase + kk + q * 4;
            float4 v;
            if (j < 1024) {
                if (kg < 512) v = *(const float4*)(W_w + j * 512 + kg);
                else          v = *(const float4*)(U_w + j * 512 + (kg - 512));
            } else {
                if (kg < 512) v = *(const float4*)(w_w + (j - 1024) * 512 + kg);
                else          v = make_float4(0.f, 0.f, 0.f, 0.f);
            }
            float* dst = &Bs[(q * 4) * 132 + jj];
            dst[0] = v.x; dst[132] = v.y; dst[2*132] = v.z; dst[3*132] = v.w;
        }
        __syncthreads();

#pragma unroll
        for (int kc = 0; kc < 16; ++kc) {
            float4 a0 = *(const float4*)&As[kc * 132 + ty * 8];
            float4 a1 = *(const float4*)&As[kc * 132 + ty * 8 + 4];
            float4 b0 = *(const float4*)&Bs[kc * 132 + tx * 8];
            float4 b1 = *(const float4*)&Bs[kc * 132 + tx * 8 + 4];
            float av[8] = {a0.x, a0.y, a0.z, a0.w, a1.x, a1.y, a1.z, a1.w};
            float bv[8] = {b0.x, b0.y, b0.z, b0.w, b1.x, b1.y, b1.z, b1.w};
#pragma unroll
            for (int r = 0; r < 8; ++r)
#pragma unroll
                for (int s = 0; s < 8; ++s) acc[r][s] += av[r] * bv[s];
        }
        __syncthreads();
    }

#pragma unroll
    for (int r = 0; r < 8; ++r) {
        int bb = ty * 8 + r;
        float* dst = &g_part[(ks * 128 + bb) * NOUT + nt * 128 + tx * 8];
        *(float4*)dst       = make_float4(acc[r][0], acc[r][1], acc[r][2], acc[r][3]);
        *(float4*)(dst + 4) = make_float4(acc[r][4], acc[r][5], acc[r][6], acc[r][7]);
    }
}

// ---------------- K2b: vectorized reduce + activation -----------------------------
__global__ void k_fo_fin(const float* __restrict__ U_b)
{
    int idx = blockIdx.x * blockDim.x + threadIdx.x;   // 0..49151 (j quads)
    int b  = idx / (NOUT / 4);
    int j4 = idx - b * (NOUT / 4);
    int j  = j4 * 4;
    float4 s = make_float4(0.f, 0.f, 0.f, 0.f);
#pragma unroll
    for (int ks = 0; ks < K2_SPLITS; ++ks) {
        float4 v = *(const float4*)&g_part[(ks * 128 + b) * NOUT + j];
        s.x += v.x; s.y += v.y; s.z += v.z; s.w += v.w;
    }
    if (j < 1024) {
        float4 ub = *(const float4*)&U_b[j];
        s.x = fast_rcp(1.f + fast_exp(-(s.x + ub.x)));
        s.y = fast_rcp(1.f + fast_exp(-(s.y + ub.y)));
        s.z = fast_rcp(1.f + fast_exp(-(s.z + ub.z)));
        s.w = fast_rcp(1.f + fast_exp(-(s.w + ub.w)));
        if (j < 512) *(float4*)&g_f[b * 512 + j]         = s;
        else         *(float4*)&g_o[b * 512 + (j - 512)] = s;
    } else {
        *(float4*)&g_a[b * 512 + (j - 1024)] = s;
    }
}

// ---------------- K3: fp16 mma, M split across 2 CTAs (2 CTAs/SM) -----------------
// CTA = (64-col H tile, 256-row W slice, batch). 256 threads, 8 warps.
#define KCH     64
#define NCHUNK  8
// float offsets in dynamic smem
#define OFF_ADD_F  0               // 64 floats
#define OFF_R1_F   64              // 8 segs x 64 cols
#define OFF_R2_F   576
#define SM_STAGE_B 4608            // stages: A 32KB + B 8KB, x2
#define A_BYTES    32768
#define STAGE_BYTES 40960
#define S2_STRIDE  33              // half2 words per row
#define K3_SMEM_BYTES (SM_STAGE_B + 2 * STAGE_BYTES)   // 86528

__global__ void __launch_bounds__(256, 2)
k_main(const float* __restrict__ c, const float* __restrict__ u_b)
{
    extern __shared__ __align__(128) float sm[];
    const uint32_t smb = (uint32_t)__cvta_generic_to_shared(sm);

    const int ht0  = blockIdx.x * 64;
    const int ws   = blockIdx.y;      // 0/1 : 256-row W slice
    const int b    = blockIdx.z;
    const int tid  = threadIdx.x;
    const int wid  = tid >> 5;
    const int lane = tid & 31;
    const int wm   = wid >> 1;        // 0..3 : 64-row M block
    const int wn   = wid & 1;         // 0..1 : 32-col N block
    const int g4   = lane >> 2;
    const int t4   = lane & 3;

    const __half* hbs = g_h16 + (size_t)b * WH + (size_t)ws * 256 * HDIM;

    if (tid < 64)
        sm[OFF_ADD_F + tid] = g_a[b * HDIM + ht0 + tid] + u_b[ht0 + tid];

    // ---- cp.async staging ----
    const int crow = tid >> 3;        // 0..31
    const int aq   = tid & 7;
    const int brow = tid >> 2;        // 0..63
    const int bq0  = (tid & 3) * 2;

    auto load_chunk = [&](int ch, int st) {
        const uint32_t sa = smb + SM_STAGE_B + (uint32_t)st * STAGE_BYTES;
        const __half* gA = hbs + ch * KCH + aq * 8;
#pragma unroll
        for (int p = 0; p < 8; ++p) {
            int row = crow + p * 32;
            cp16(sa + (uint32_t)(row * 128 + ((aq ^ (row & 7)) << 4)),
                 gA + (size_t)row * HDIM);
        }
        const uint32_t sb = sa + A_BYTES;
        const __half* gB = g_uw16 + (size_t)(ht0 + brow) * HDIM + ch * KCH;
#pragma unroll
        for (int i = 0; i < 2; ++i) {
            int q = bq0 + i;
            cp16(sb + (uint32_t)(brow * 128 + ((q ^ (brow & 7)) << 4)), gB + q * 8);
        }
        cp_commit();
    };

    // ---- ldmatrix per-lane bases ----
    const int lane15 = lane & 15;
    const int laneQA = lane >> 4;
    const int laneQB = (lane >> 3) & 1;

    uint32_t aBase[4], aRL[4];
#pragma unroll
    for (int tm = 0; tm < 4; ++tm) {
        int row = wm * 64 + tm * 16 + lane15;
        aRL[tm]   = row & 7;
        aBase[tm] = smb + SM_STAGE_B + (uint32_t)(row * 128);
    }
    uint32_t bBase[2], bRL[2];
#pragma unroll
    for (int p = 0; p < 2; ++p) {
        int row = wn * 32 + p * 16 + ((lane >> 4) << 3) + (lane & 7);
        bRL[p]   = row & 7;
        bBase[p] = smb + SM_STAGE_B + A_BYTES + (uint32_t)(row * 128);
    }

    float acc[4][4][4];
#pragma unroll
    for (int i = 0; i < 4; ++i)
#pragma unroll
        for (int j = 0; j < 4; ++j)
#pragma unroll
            for (int r = 0; r < 4; ++r) acc[i][j][r] = 0.f;

    // ---- 2-stage pipeline ----
    load_chunk(0, 0);
    load_chunk(1, 1);

    for (int ch = 0; ch < NCHUNK; ++ch) {
        const int st = ch & 1;
        if (ch == NCHUNK - 1) cp_wait<0>(); else cp_wait<1>();
        __syncthreads();

        const uint32_t off = (uint32_t)st * STAGE_BYTES;
#pragma unroll
        for (int ks = 0; ks < 4; ++ks) {
            const uint32_t qb = (uint32_t)(ks * 2);
            uint32_t af[4][4], bf[4][2];
#pragma unroll
            for (int tm = 0; tm < 4; ++tm)
                ldsm_x4(af[tm], aBase[tm] + off + (((qb + laneQA) ^ aRL[tm]) << 4));
#pragma unroll
            for (int p = 0; p < 2; ++p) {
                uint32_t tmp[4];
                ldsm_x4(tmp, bBase[p] + off + (((qb + laneQB) ^ bRL[p]) << 4));
                bf[2 * p][0] = tmp[0];     bf[2 * p][1] = tmp[1];
                bf[2 * p + 1][0] = tmp[2]; bf[2 * p + 1][1] = tmp[3];
            }
#pragma unroll
            for (int tm = 0; tm < 4; ++tm)
#pragma unroll
                for (int tn = 0; tn < 4; ++tn)
                    mma_f16(acc[tm][tn], af[tm], bf[tn]);
        }
        __syncthreads();
        if (ch + 2 < NCHUNK) load_chunk(ch + 2, st);
    }

    // ---- epilogue: exp(sigmoid(x)) ∝ exp2(K*tanh(x/2)); sqrt(e) cancels ----------
    __half2* S2 = (__half2*)(sm + SM_STAGE_B / 4);   // 256 x 33 half2, aliases stages
    const float KE = 0.72134752f;     // 0.5 * log2(e)
#pragma unroll
    for (int tm = 0; tm < 4; ++tm) {
#pragma unroll
        for (int tn = 0; tn < 4; ++tn) {
            int colb = wn * 32 + tn * 8 + t4 * 2;
            float add0 = sm[OFF_ADD_F + colb];
            float add1 = sm[OFF_ADD_F + colb + 1];
#pragma unroll
            for (int r = 0; r < 2; ++r) {
                int w = wm * 64 + tm * 16 + g4 + r * 8;
                float x0 = acc[tm][tn][r * 2 + 0] + add0;
                float x1 = acc[tm][tn][r * 2 + 1] + add1;
                float s0 = ex2_mufu(KE * tanh_mufu(0.5f * x0));
                float s1 = ex2_mufu(KE * tanh_mufu(0.5f * x1));
                S2[w * S2_STRIDE + (colb >> 1)] = __floats2half2_rn(s0, s1);
            }
        }
    }
    __syncthreads();

    // ---- partial softmax denominator + weighted-c numerator over 256 rows --------
    const int colp = tid & 31;        // column pair
    const int seg  = tid >> 5;        // 8 segments x 32 w
    const float* cbase = c + (size_t)b * WH + (size_t)ws * 256 * HDIM
                       + ht0 + colp * 2;
    float dsx = 0.f, dsy = 0.f, wsx = 0.f, wsy = 0.f;
#pragma unroll 4
    for (int ww = 0; ww < 32; ++ww) {
        int w = seg * 32 + ww;
        float2 e  = __half22float2(S2[w * S2_STRIDE + colp]);
        float2 cv = *(const float2*)(cbase + (size_t)w * HDIM);
        dsx += e.x; dsy += e.y;
        wsx += e.x * cv.x; wsy += e.y * cv.y;
    }
    __syncthreads();   // S2 reads complete before header region rewrite below
    *(float2*)&sm[OFF_R1_F + seg * 64 + colp * 2] = make_float2(dsx, dsy);
    *(float2*)&sm[OFF_R2_F + seg * 64 + colp * 2] = make_float2(wsx, wsy);
    __syncthreads();

    if (tid < 64) {
        float dt = 0.f, wt = 0.f;
#pragma unroll
        for (int s2 = 0; s2 < 8; ++s2) {
            dt += sm[OFF_R1_F + s2 * 64 + tid];
            wt += sm[OFF_R2_F + s2 * 64 + tid];
        }
        int gi = (ws * BATCH + b) * HDIM + ht0 + tid;
        g_red1[gi] = dt;
        g_red2[gi] = wt;
    }
}

// ---------------- K4: combine partials -> outputs ---------------------------------
__global__ void k_comb(const float* __restrict__ c_g, float* __restrict__ out)
{
    int idx = blockIdx.x * blockDim.x + threadIdx.x;   // 0..65535
    float dt = g_red1[idx] + g_red1[BATCH * HDIM + idx];
    float wt = g_red2[idx] + g_red2[BATCH * HDIM + idx];
    float newc = g_f[idx] * c_g[idx] + wt / dt;
    out[BATCH * HDIM + idx] = newc;            // new_c
    out[idx] = g_o[idx] * tanhf(newc);         // new_g
}

// ---------------- launch -----------------------------------------------------------
extern "C" void kernel_launch(void* const* d_in, const int* in_sizes, int n_in,
                              void* d_out, int out_size)
{
    const float* g   = (const float*)d_in[0];
    const float* c_g = (const float*)d_in[1];
    const float* h   = (const float*)d_in[2];
    const float* c   = (const float*)d_in[3];
    const float* W_w = (const float*)d_in[4];
    const float* w_w = (const float*)d_in[5];
    const float* U_w = (const float*)d_in[6];
    const float* U_b = (const float*)d_in[7];
    const float* u_w = (const float*)d_in[8];
    const float* u_b = (const float*)d_in[9];
    float* out = (float*)d_out;

    (void)in_sizes; (void)n_in; (void)out_size;

    k_prep<<<544, 256>>>(h, u_w);
    k_fo<<<dim3(12, 16), 256>>>(g, W_w, U_w, w_w);
    k_fo_fin<<<192, 256>>>(U_b);

    static int smem_set = 0;
    if (!smem_set) {
        cudaFuncSetAttribute(k_main, cudaFuncAttributeMaxDynamicSharedMemorySize,
                             K3_SMEM_BYTES);
        smem_set = 1;
    }
    k_main<<<dim3(8, 2, 128), 256, K3_SMEM_BYTES>>>(c, u_b);
    k_comb<<<256, 256>>>(c_g, out);
}